// round 10
// baseline (speedup 1.0000x reference)
#include <cuda_runtime.h>
#include <cuda_fp16.h>
#include <math.h>
#include <stdint.h>

#define B_   16
#define S_   512
#define H_   768
#define NH_  12
#define L_   6
#define FF_  3072
#define DH_  64
#define LAB_ 10
#define QKVN 2304          // 3*H

// ---------------- scratch (device globals; no allocations allowed) ----------
__device__ float  g_x   [(size_t)B_*S_*H_];
__device__ __half g_xh  [(size_t)B_*S_*H_];
__device__ __half g_qkv [(size_t)B_*S_*QKVN];
__device__ __half g_ctxh[(size_t)B_*S_*H_];
__device__ float  g_tmp [(size_t)B_*S_*H_];
__device__ __half g_ffh [(size_t)B_*S_*FF_];
__device__ float  g_hidden[(size_t)B_*H_];
__device__ float  g_logits[(size_t)B_*LAB_];
// transposed + fp16 weights [N][K]
__device__ __half g_wqkvT[(size_t)L_*QKVN*H_];
__device__ __half g_woT  [(size_t)L_*H_*H_];
__device__ __half g_wf1T [(size_t)L_*FF_*H_];
__device__ __half g_wf2T [(size_t)L_*H_*FF_];
__device__ float  g_bqkv [(size_t)L_*QKVN];

// ---------------- small helpers ----------------
__device__ __forceinline__ uint32_t smem_u32(const void* p) {
    return (uint32_t)__cvta_generic_to_shared(p);
}

__device__ __forceinline__ void cp16s(uint32_t s, const void* g) {
    asm volatile("cp.async.ca.shared.global [%0], [%1], 16;\n" :: "r"(s), "l"(g));
}

__device__ __forceinline__ void ldsm4(uint32_t* r, uint32_t a) {
    asm volatile("ldmatrix.sync.aligned.m8n8.x4.shared.b16 {%0,%1,%2,%3}, [%4];"
                 : "=r"(r[0]), "=r"(r[1]), "=r"(r[2]), "=r"(r[3]) : "r"(a));
}

__device__ __forceinline__ void ldsm4t(uint32_t* r, uint32_t a) {
    asm volatile("ldmatrix.sync.aligned.m8n8.x4.trans.shared.b16 {%0,%1,%2,%3}, [%4];"
                 : "=r"(r[0]), "=r"(r[1]), "=r"(r[2]), "=r"(r[3]) : "r"(a));
}

__device__ __forceinline__ void mma_f16(float* c, const uint32_t* a, const uint32_t* b) {
    asm volatile(
        "mma.sync.aligned.m16n8k16.row.col.f32.f16.f16.f32 "
        "{%0,%1,%2,%3}, {%4,%5,%6,%7}, {%8,%9}, {%0,%1,%2,%3};\n"
        : "+f"(c[0]), "+f"(c[1]), "+f"(c[2]), "+f"(c[3])
        : "r"(a[0]), "r"(a[1]), "r"(a[2]), "r"(a[3]), "r"(b[0]), "r"(b[1]));
}

__device__ __forceinline__ float gelu_tanh(float v) {
    float c = v * v * v;
    return 0.5f * v * (1.f + tanhf(0.7978845608028654f * (v + 0.044715f * c)));
}

__device__ __forceinline__ float warp_sum(float v) {
    #pragma unroll
    for (int o = 16; o; o >>= 1) v += __shfl_xor_sync(0xffffffffu, v, o);
    return v;
}

// ---------------- weight transpose + fp16 convert ----------------
__global__ void transpose_cvt(const float* __restrict__ in, __half* __restrict__ out,
                              int R, int C, long ozs)
{
    in  += (size_t)blockIdx.z * R * C;
    out += (size_t)blockIdx.z * ozs;
    __shared__ float t[32][33];
    int c0 = blockIdx.x * 32, r0 = blockIdx.y * 32;
    int tx = threadIdx.x, ty = threadIdx.y;
    #pragma unroll
    for (int i = 0; i < 32; i += 8)
        t[ty + i][tx] = in[(size_t)(r0 + ty + i) * C + c0 + tx];
    __syncthreads();
    #pragma unroll
    for (int i = 0; i < 32; i += 8)
        out[(size_t)(c0 + ty + i) * R + r0 + tx] = __float2half_rn(t[tx][ty + i]);
}

__global__ void concat_bias(const float* __restrict__ bq, const float* __restrict__ bk,
                            const float* __restrict__ bv, float* __restrict__ out)
{
    int i = blockIdx.x * 256 + threadIdx.x;
    if (i >= L_ * QKVN) return;
    int l = i / QKVN, r = i - l * QKVN;
    float val;
    if (r < H_)            val = bq[l * H_ + r];
    else if (r < 2 * H_)   val = bk[l * H_ + r - H_];
    else                   val = bv[l * H_ + r - 2 * H_];
    out[i] = val;
}

// ---------------- embedding + LN + selection (warp per token) ----------------
__global__ void embed_kernel(const int* __restrict__ src, const int* __restrict__ seg,
                             const int* __restrict__ tib,
                             const float* __restrict__ we, const float* __restrict__ pe,
                             const float* __restrict__ se,
                             const float* __restrict__ g, const float* __restrict__ bta,
                             const float* __restrict__ sel, float* __restrict__ x,
                             __half* __restrict__ xh)
{
    int t = blockIdx.x * 8 + (threadIdx.x >> 5);
    int lane = threadIdx.x & 31;
    int s = t % S_;
    int w = src[t], sg = seg[t];
    const float4* wr = (const float4*)(we + (size_t)w * H_);
    const float4* pr = (const float4*)(pe + (size_t)s * H_);
    const float4* sr = (const float4*)(se + (size_t)sg * H_);
    float4 v[6];
    float lsum = 0.f, lsq = 0.f;
    #pragma unroll
    for (int i = 0; i < 6; i++) {
        int idx = lane + 32 * i;
        float4 a = wr[idx], bv4 = pr[idx], c = sr[idx];
        v[i].x = a.x + bv4.x + c.x; v[i].y = a.y + bv4.y + c.y;
        v[i].z = a.z + bv4.z + c.z; v[i].w = a.w + bv4.w + c.w;
        lsum += v[i].x + v[i].y + v[i].z + v[i].w;
        lsq  += v[i].x*v[i].x + v[i].y*v[i].y + v[i].z*v[i].z + v[i].w*v[i].w;
    }
    float tot = warp_sum(lsum), totsq = warp_sum(lsq);
    float mean = tot / H_;
    float var  = totsq / H_ - mean * mean;
    float inv  = rsqrtf(var + 1e-5f);
    float f = sel[tib[t]];
    float4* xo = (float4*)(x + (size_t)t * H_);
    uint2*  xho = (uint2*)(xh + (size_t)t * H_);
    const float4* g4 = (const float4*)g;
    const float4* b4 = (const float4*)bta;
    #pragma unroll
    for (int i = 0; i < 6; i++) {
        int idx = lane + 32 * i;
        float4 gg = g4[idx], bb = b4[idx], o;
        o.x = ((v[i].x - mean) * inv * gg.x + bb.x) * f;
        o.y = ((v[i].y - mean) * inv * gg.y + bb.y) * f;
        o.z = ((v[i].z - mean) * inv * gg.z + bb.z) * f;
        o.w = ((v[i].w - mean) * inv * gg.w + bb.w) * f;
        xo[idx] = o;
        __half2 h0 = __floats2half2_rn(o.x, o.y);
        __half2 h1 = __floats2half2_rn(o.z, o.w);
        uint2 u; u.x = *(uint32_t*)&h0; u.y = *(uint32_t*)&h1;
        xho[idx] = u;
    }
}

// ---------------- LN over tmp (residual already fused in GEMM) --------------
__global__ void ln_kernel(const float* __restrict__ t,
                          const float* __restrict__ g, const float* __restrict__ bta,
                          float* __restrict__ x, __half* __restrict__ xh)
{
    int row = blockIdx.x * 8 + (threadIdx.x >> 5);
    int lane = threadIdx.x & 31;
    const float4* tr = (const float4*)(t + (size_t)row * H_);
    float4 v[6];
    float lsum = 0.f, lsq = 0.f;
    #pragma unroll
    for (int i = 0; i < 6; i++) {
        v[i] = tr[lane + 32 * i];
        lsum += v[i].x + v[i].y + v[i].z + v[i].w;
        lsq  += v[i].x*v[i].x + v[i].y*v[i].y + v[i].z*v[i].z + v[i].w*v[i].w;
    }
    float tot = warp_sum(lsum), totsq = warp_sum(lsq);
    float mean = tot / H_;
    float var  = totsq / H_ - mean * mean;
    float inv  = rsqrtf(var + 1e-5f);
    float4* xo = (float4*)(x + (size_t)row * H_);
    uint2*  xho = (uint2*)(xh + (size_t)row * H_);
    const float4* g4 = (const float4*)g;
    const float4* b4 = (const float4*)bta;
    #pragma unroll
    for (int i = 0; i < 6; i++) {
        int idx = lane + 32 * i;
        float4 gg = g4[idx], bb = b4[idx], o;
        o.x = (v[i].x - mean) * inv * gg.x + bb.x;
        o.y = (v[i].y - mean) * inv * gg.y + bb.y;
        o.z = (v[i].z - mean) * inv * gg.z + bb.z;
        o.w = (v[i].w - mean) * inv * gg.w + bb.w;
        xo[idx] = o;
        __half2 h0 = __floats2half2_rn(o.x, o.y);
        __half2 h1 = __floats2half2_rn(o.z, o.w);
        uint2 u; u.x = *(uint32_t*)&h0; u.y = *(uint32_t*)&h1;
        xho[idx] = u;
    }
}

// =====================================================================
// FP16 tensor-core GEMM: out = act(A[M,K] @ Bw[N,K]^T + bias [+ Res])
// BM=128, BN in {128,64}, BK=64 halves, 256 threads.
// BN=128: warp tile 32x64 ; BN=64: warp tile 32x32 (smaller grid-quantization
// loss for N=768 layers). m16n8k16, 3-stage cp.async, XOR-swizzled 128B rows,
// one __syncthreads per k-tile.
// ACT: 0 none, 1 gelu. OUTH: 1 half out, 0 float out. RES: add Res.
// =====================================================================
template<int ACT, int OUTH, int RES, int BN>
__global__ void __launch_bounds__(256)
hgemm(const __half* __restrict__ A, const __half* __restrict__ Bw,
      const float* __restrict__ bias, void* __restrict__ Cout,
      const float* __restrict__ Res,
      int K, int lda, int ldb, int ldc)
{
    constexpr int BSTG = BN * 128;          // bytes per B stage
    constexpr int STG  = 16384 + BSTG;      // bytes per stage (A + B)
    constexpr int NF   = BN / 16;           // b-fragment count (8 or 4)
    constexpr int NP   = NF / 2;            // ldsm ops per ks (4 or 2)
    constexpr int BCH  = BN * 128 / 16 / 256; // B copy iters (4 or 2)

    extern __shared__ char smem[];
    const uint32_t sb = smem_u32(smem);

    const int m0  = blockIdx.y * 128;
    const int n0  = blockIdx.x * BN;
    const int tid = threadIdx.x;
    const int lane = tid & 31, wid = tid >> 5;
    const int wm = wid & 3, wn = wid >> 2;
    const int g = lane >> 2, t = lane & 3;

    const int nt = K >> 6;     // BK = 64 halves = 128B rows

    auto load_st = [&](int kt) {
        int st = kt % 3;
        int k0 = kt << 6;
        uint32_t ab = sb + st * STG;
        uint32_t bb = ab + 16384;
        #pragma unroll
        for (int i = 0; i < 4; i++) {
            int c = i * 256 + tid;              // 1024 chunks for A
            int row = c >> 3, ch = c & 7;
            uint32_t d = ((uint32_t)row << 7) + (uint32_t)((ch ^ (row & 7)) << 4);
            cp16s(ab + d, A + (size_t)(m0 + row) * lda + k0 + ch * 8);
        }
        #pragma unroll
        for (int i = 0; i < BCH; i++) {
            int c = i * 256 + tid;              // BN*8 chunks for B
            int row = c >> 3, ch = c & 7;
            uint32_t d = ((uint32_t)row << 7) + (uint32_t)((ch ^ (row & 7)) << 4);
            cp16s(bb + d, Bw + (size_t)(n0 + row) * ldb + k0 + ch * 8);
        }
        asm volatile("cp.async.commit_group;" ::: "memory");
    };

    float acc[2][NF][4];
    #pragma unroll
    for (int i = 0; i < 2; i++)
        #pragma unroll
        for (int j = 0; j < NF; j++)
            #pragma unroll
            for (int r = 0; r < 4; r++) acc[i][j][r] = 0.f;

    load_st(0);
    if (nt > 1) load_st(1);

    const int arow_b = wm * 32 + (lane & 15);                           // + mt*16
    const int achk_b = (lane >> 4);                                     // + ks*2
    const int brow_b = wn * (BN / 2) + ((lane >> 4) << 3) + (lane & 7); // + p*16
    const int bchk_b = ((lane >> 3) & 1);                               // + ks*2

    for (int kt = 0; kt < nt; kt++) {
        int st = kt % 3;
        if (kt + 1 < nt)
            asm volatile("cp.async.wait_group 1;" ::: "memory");
        else
            asm volatile("cp.async.wait_group 0;" ::: "memory");
        __syncthreads();
        if (kt + 2 < nt) load_st(kt + 2);

        uint32_t ab = sb + st * STG;
        uint32_t bb = ab + 16384;

        #pragma unroll
        for (int ks = 0; ks < 4; ks++) {
            uint32_t afr[2][4];
            #pragma unroll
            for (int mt = 0; mt < 2; mt++) {
                int row = arow_b + mt * 16;
                int ch  = achk_b + ks * 2;
                ldsm4(afr[mt], ab + ((uint32_t)row << 7)
                                  + (uint32_t)((ch ^ (row & 7)) << 4));
            }
            uint32_t bfr[NF][2];
            #pragma unroll
            for (int p = 0; p < NP; p++) {
                int row = brow_b + p * 16;
                int ch  = bchk_b + ks * 2;
                uint32_t rr[4];
                ldsm4(rr, bb + ((uint32_t)row << 7)
                             + (uint32_t)((ch ^ (row & 7)) << 4));
                bfr[2 * p][0]     = rr[0]; bfr[2 * p][1]     = rr[1];
                bfr[2 * p + 1][0] = rr[2]; bfr[2 * p + 1][1] = rr[3];
            }
            #pragma unroll
            for (int mt = 0; mt < 2; mt++)
                #pragma unroll
                for (int ntl = 0; ntl < NF; ntl++)
                    mma_f16(acc[mt][ntl], afr[mt], bfr[ntl]);
        }
    }

    #pragma unroll
    for (int mt = 0; mt < 2; mt++) {
        #pragma unroll
        for (int ntl = 0; ntl < NF; ntl++) {
            int row = m0 + wm * 32 + mt * 16 + g;
            int col = n0 + wn * (BN / 2) + ntl * 8 + t * 2;
            float bv0 = bias[col], bv1 = bias[col + 1];
            #pragma unroll
            for (int half_ = 0; half_ < 2; half_++) {
                int r = row + half_ * 8;
                float v0 = acc[mt][ntl][half_ * 2 + 0] + bv0;
                float v1 = acc[mt][ntl][half_ * 2 + 1] + bv1;
                if (ACT == 1) { v0 = gelu_tanh(v0); v1 = gelu_tanh(v1); }
                if (RES) {
                    float2 rr = *(const float2*)&Res[(size_t)r * ldc + col];
                    v0 += rr.x; v1 += rr.y;
                }
                if (OUTH) {
                    __half2* C = (__half2*)((__half*)Cout + (size_t)r * ldc + col);
                    *C = __floats2half2_rn(v0, v1);
                } else {
                    float* C = (float*)Cout + (size_t)r * ldc + col;
                    *(float2*)C = make_float2(v0, v1);
                }
            }
        }
    }
}

#define HG_SMEM128 98304   // 3 * (16KB A + 16KB B)
#define HG_SMEM64  73728   // 3 * (16KB A + 8KB B)

// =====================================================================
// Fused flash-attention, fp16 operands / fp32 softmax+accum (as R9).
// =====================================================================
#define ATTN_SMEM  ((128*72 + 2*64*72 + 2*64*72) * 2 + 512 * 4)   // 57344

__global__ void __launch_bounds__(256)
attn_kernel(const __half* __restrict__ qkv, const int* __restrict__ seg,
            __half* __restrict__ ctx)
{
    extern __shared__ __half hsm[];
    __half* sP    = hsm;
    __half* sK    = sP + 128 * 72;
    __half* sV    = sK + 2 * 64 * 72;
    float*  smask = (float*)(sV + 2 * 64 * 72);

    const int bh = blockIdx.y;
    const int b = bh / NH_, h = bh - b * NH_;
    const int q0 = blockIdx.x * 128;

    const __half* qp = qkv + (size_t)b * S_ * QKVN + h * DH_;
    const __half* kp = qp + H_;
    __half* cp = ctx + ((size_t)b * S_ + q0) * H_ + h * DH_;

    const int tid = threadIdx.x, lane = tid & 31, wid = tid >> 5;
    const int g = lane >> 2, t = lane & 3;
    const uint32_t sPb = smem_u32(sP);
    const uint32_t sKb0 = smem_u32(sK);
    const uint32_t sVb0 = smem_u32(sV);

    for (int i = tid; i < S_; i += 256)
        smask[i] = (seg[b * S_ + i] > 0) ? 0.f : -1e9f;

    #pragma unroll
    for (int i = 0; i < 4; i++) {
        int c = i * 256 + tid;
        int row = c >> 3, kc = (c & 7) << 3;
        cp16s(sPb + (uint32_t)row * 144 + ((c & 7) << 4),
              qp + (size_t)(q0 + row) * QKVN + kc);
    }
    asm volatile("cp.async.commit_group;" ::: "memory");
    asm volatile("cp.async.wait_group 0;" ::: "memory");
    __syncthreads();

    const uint32_t a_base = (uint32_t)(wid * 16 + (lane & 15)) * 144 + ((lane >> 4) << 4);
    uint32_t qf[4][4];
    #pragma unroll
    for (int s = 0; s < 4; s++)
        ldsm4(qf[s], sPb + a_base + s * 32);
    __syncthreads();

    auto load_kv = [&](int kt, int buf) {
        int kbase = kt * 64;
        #pragma unroll
        for (int i = 0; i < 2; i++) {
            int c = i * 256 + tid;
            int row = c >> 3, kc = (c & 7) << 3;
            const __half* kg = kp + (size_t)(kbase + row) * QKVN + kc;
            uint32_t d = (uint32_t)row * 144 + ((c & 7) << 4);
            cp16s(sKb0 + buf * 9216 + d, kg);
            cp16s(sVb0 + buf * 9216 + d, kg + H_);
        }
        asm volatile("cp.async.commit_group;" ::: "memory");
    };
    load_kv(0, 0);

    const uint32_t bK_base = (uint32_t)(((lane >> 4) << 3) + (lane & 7)) * 144
                           + (((lane >> 3) & 1) << 4);
    const uint32_t bV_base = (uint32_t)(lane & 15) * 144 + (((lane >> 4) & 1) << 4);

    float m_run[2] = {-1e30f, -1e30f};
    float l_run[2] = {0.f, 0.f};
    float o[8][4];
    #pragma unroll
    for (int ntl = 0; ntl < 8; ntl++)
        #pragma unroll
        for (int r = 0; r < 4; r++) o[ntl][r] = 0.f;

    for (int kt = 0; kt < S_ / 64; kt++) {
        int buf = kt & 1;
        asm volatile("cp.async.wait_group 0;" ::: "memory");
        __syncthreads();
        if (kt + 1 < S_ / 64) load_kv(kt + 1, buf ^ 1);

        uint32_t sKb = sKb0 + buf * 9216;
        uint32_t sVb = sVb0 + buf * 9216;

        float sacc[8][4];
        #pragma unroll
        for (int ntl = 0; ntl < 8; ntl++)
            #pragma unroll
            for (int r = 0; r < 4; r++) sacc[ntl][r] = 0.f;
        #pragma unroll
        for (int s = 0; s < 4; s++) {
            uint32_t bfr[8][2];
            #pragma unroll
            for (int p = 0; p < 4; p++) {
                uint32_t rr[4];
                ldsm4(rr, sKb + bK_base + p * (16 * 144) + s * 32);
                bfr[2 * p][0]     = rr[0]; bfr[2 * p][1]     = rr[1];
                bfr[2 * p + 1][0] = rr[2]; bfr[2 * p + 1][1] = rr[3];
            }
            #pragma unroll
            for (int ntl = 0; ntl < 8; ntl++)
                mma_f16(sacc[ntl], qf[s], bfr[ntl]);
        }

        float tmax0 = -1e30f, tmax1 = -1e30f;
        #pragma unroll
        for (int ntl = 0; ntl < 8; ntl++) {
            int col = kt * 64 + ntl * 8 + t * 2;
            float mb0 = smask[col], mb1 = smask[col + 1];
            sacc[ntl][0] = fmaf(sacc[ntl][0], 0.125f, mb0);
            sacc[ntl][1] = fmaf(sacc[ntl][1], 0.125f, mb1);
            sacc[ntl][2] = fmaf(sacc[ntl][2], 0.125f, mb0);
            sacc[ntl][3] = fmaf(sacc[ntl][3], 0.125f, mb1);
            tmax0 = fmaxf(tmax0, fmaxf(sacc[ntl][0], sacc[ntl][1]));
            tmax1 = fmaxf(tmax1, fmaxf(sacc[ntl][2], sacc[ntl][3]));
        }
        tmax0 = fmaxf(tmax0, __shfl_xor_sync(0xffffffffu, tmax0, 1));
        tmax0 = fmaxf(tmax0, __shfl_xor_sync(0xffffffffu, tmax0, 2));
        tmax1 = fmaxf(tmax1, __shfl_xor_sync(0xffffffffu, tmax1, 1));
        tmax1 = fmaxf(tmax1, __shfl_xor_sync(0xffffffffu, tmax1, 2));
        float mnew0 = fmaxf(m_run[0], tmax0);
        float mnew1 = fmaxf(m_run[1], tmax1);
        float al0 = __expf(m_run[0] - mnew0);
        float al1 = __expf(m_run[1] - mnew1);
        float ts0 = 0.f, ts1 = 0.f;
        #pragma unroll
        for (int ntl = 0; ntl < 8; ntl++) {
            sacc[ntl][0] = __expf(sacc[ntl][0] - mnew0);
            sacc[ntl][1] = __expf(sacc[ntl][1] - mnew0);
            sacc[ntl][2] = __expf(sacc[ntl][2] - mnew1);
            sacc[ntl][3] = __expf(sacc[ntl][3] - mnew1);
            ts0 += sacc[ntl][0] + sacc[ntl][1];
            ts1 += sacc[ntl][2] + sacc[ntl][3];
        }
        ts0 += __shfl_xor_sync(0xffffffffu, ts0, 1);
        ts0 += __shfl_xor_sync(0xffffffffu, ts0, 2);
        ts1 += __shfl_xor_sync(0xffffffffu, ts1, 1);
        ts1 += __shfl_xor_sync(0xffffffffu, ts1, 2);
        l_run[0] = l_run[0] * al0 + ts0;
        l_run[1] = l_run[1] * al1 + ts1;
        m_run[0] = mnew0; m_run[1] = mnew1;
        #pragma unroll
        for (int ntl = 0; ntl < 8; ntl++) {
            o[ntl][0] *= al0; o[ntl][1] *= al0;
            o[ntl][2] *= al1; o[ntl][3] *= al1;
        }

        __half* pw = sP + (size_t)(wid * 16) * 72;
        #pragma unroll
        for (int ntl = 0; ntl < 8; ntl++) {
            int c0 = ntl * 8 + t * 2;
            *(__half2*)&pw[g * 72 + c0]       = __floats2half2_rn(sacc[ntl][0], sacc[ntl][1]);
            *(__half2*)&pw[(g + 8) * 72 + c0] = __floats2half2_rn(sacc[ntl][2], sacc[ntl][3]);
        }
        __syncwarp();
        #pragma unroll
        for (int s = 0; s < 4; s++) {
            uint32_t pf[4];
            ldsm4(pf, sPb + a_base + s * 32);
            uint32_t bfr[8][2];
            #pragma unroll
            for (int p = 0; p < 4; p++) {
                uint32_t rr[4];
                ldsm4t(rr, sVb + bV_base + s * (16 * 144) + p * 32);
                bfr[2 * p][0]     = rr[0]; bfr[2 * p][1]     = rr[1];
                bfr[2 * p + 1][0] = rr[2]; bfr[2 * p + 1][1] = rr[3];
            }
            #pragma unroll
            for (int ntl = 0; ntl < 8; ntl++)
                mma_f16(o[ntl], pf, bfr[ntl]);
        }
    }

    float rl0 = 1.f / l_run[0], rl1 = 1.f / l_run[1];
    int r0 = wid * 16 + g;
    #pragma unroll
    for (int ntl = 0; ntl < 8; ntl++) {
        int col = ntl * 8 + t * 2;
        *(__half2*)&cp[(size_t)r0 * H_ + col] =
            __floats2half2_rn(o[ntl][0] * rl0, o[ntl][1] * rl0);
        *(__half2*)&cp[(size_t)(r0 + 8) * H_ + col] =
            __floats2half2_rn(o[ntl][2] * rl1, o[ntl][3] * rl1);
    }
}

// ---------------- small SIMT GEMM (pooler + classifier only) ----------------
template<int ACT> // 0 none, 2 tanh
__global__ void gemm_kernel(const float* __restrict__ A, const float* __restrict__ Bm,
                            const float* __restrict__ bias, float* __restrict__ C,
                            int M, int N, int K, int lda, int ldb, int ldc)
{
    __shared__ float As[16][65];
    __shared__ float Bs[16][65];

    int m0 = blockIdx.y * 64;
    int n0 = blockIdx.x * 64;
    int tid = threadIdx.x;
    int tx = tid & 15, ty = tid >> 4;

    float acc[4][4] = {};

    for (int k0 = 0; k0 < K; k0 += 16) {
        #pragma unroll
        for (int i = tid; i < 64 * 16; i += 256) {
            int m = i >> 4, k = i & 15;
            int gm = m0 + m, gk = k0 + k;
            As[k][m] = (gm < M && gk < K) ? A[(long)gm * lda + gk] : 0.f;
        }
        #pragma unroll
        for (int i = tid; i < 16 * 64; i += 256) {
            int k = i >> 6, n = i & 63;
            int gk = k0 + k, gn = n0 + n;
            Bs[k][n] = (gk < K && gn < N) ? Bm[(long)gk * ldb + gn] : 0.f;
        }
        __syncthreads();
        #pragma unroll
        for (int k = 0; k < 16; k++) {
            float a[4], bb[4];
            #pragma unroll
            for (int i = 0; i < 4; i++) a[i] = As[k][ty * 4 + i];
            #pragma unroll
            for (int j = 0; j < 4; j++) bb[j] = Bs[k][tx * 4 + j];
            #pragma unroll
            for (int i = 0; i < 4; i++)
                #pragma unroll
                for (int j = 0; j < 4; j++)
                    acc[i][j] = fmaf(a[i], bb[j], acc[i][j]);
        }
        __syncthreads();
    }

    #pragma unroll
    for (int i = 0; i < 4; i++) {
        int gm = m0 + ty * 4 + i;
        if (gm >= M) continue;
        #pragma unroll
        for (int j = 0; j < 4; j++) {
            int gn = n0 + tx * 4 + j;
            if (gn >= N) continue;
            float v = acc[i][j];
            if (bias) v += bias[gn];
            if (ACT == 2) v = tanhf(v);
            C[(long)gm * ldc + gn] = v;
        }
    }
}

// ---------------- log-softmax + NLL loss + output write ----------------
__global__ void loss_kernel(const float* __restrict__ logits, const int* __restrict__ tgt,
                            float* __restrict__ out, int out_size)
{
    int lane = threadIdx.x;
    float lp = 0.f;
    if (lane < B_) {
        const float* row = logits + lane * LAB_;
        float mx = row[0];
        #pragma unroll
        for (int j = 1; j < LAB_; j++) mx = fmaxf(mx, row[j]);
        float s = 0.f;
        #pragma unroll
        for (int j = 0; j < LAB_; j++) s += expf(row[j] - mx);
        lp = row[tgt[lane]] - mx - logf(s);
    }
    #pragma unroll
    for (int o = 16; o; o >>= 1) lp += __shfl_down_sync(0xffffffffu, lp, o);
    int ofs = (out_size > B_ * LAB_) ? 1 : 0;
    if (lane == 0 && ofs) out[0] = -lp / (float)B_;
    for (int i = lane; i < B_ * LAB_; i += 32) out[ofs + i] = logits[i];
}

// ---------------- host launch ----------------
extern "C" void kernel_launch(void* const* d_in, const int* in_sizes, int n_in,
                              void* d_out, int out_size)
{
    const int*   src  = (const int*)d_in[0];
    const int*   seg  = (const int*)d_in[1];
    const int*   tgt  = (const int*)d_in[2];
    const int*   tib  = (const int*)d_in[3];
    const float* we   = (const float*)d_in[4];
    const float* pe   = (const float*)d_in[5];
    const float* se   = (const float*)d_in[6];
    const float* elng = (const float*)d_in[7];
    const float* elnb = (const float*)d_in[8];
    const float* Wq   = (const float*)d_in[9];
    const float* bq   = (const float*)d_in[10];
    const float* Wk   = (const float*)d_in[11];
    const float* bk   = (const float*)d_in[12];
    const float* Wv   = (const float*)d_in[13];
    const float* bv   = (const float*)d_in[14];
    const float* Wo   = (const float*)d_in[15];
    const float* bo   = (const float*)d_in[16];
    const float* ln1g = (const float*)d_in[17];
    const float* ln1b = (const float*)d_in[18];
    const float* Wf1  = (const float*)d_in[19];
    const float* bf1  = (const float*)d_in[20];
    const float* Wf2  = (const float*)d_in[21];
    const float* bf2  = (const float*)d_in[22];
    const float* ln2g = (const float*)d_in[23];
    const float* ln2b = (const float*)d_in[24];
    const float* Wp1  = (const float*)d_in[25];
    const float* bp1  = (const float*)d_in[26];
    const float* Wp2  = (const float*)d_in[27];
    const float* bp2  = (const float*)d_in[28];
    const float* sel  = (const float*)d_in[29];
    (void)in_sizes; (void)n_in;

    float *x, *tmp, *hidden, *logits, *bqkv;
    __half *xh, *qkv, *ctxh, *ffh, *wqkvT, *woT, *wf1T, *wf2T;
    cudaGetSymbolAddress((void**)&x,     g_x);
    cudaGetSymbolAddress((void**)&xh,    g_xh);
    cudaGetSymbolAddress((void**)&qkv,   g_qkv);
    cudaGetSymbolAddress((void**)&ctxh,  g_ctxh);
    cudaGetSymbolAddress((void**)&tmp,   g_tmp);
    cudaGetSymbolAddress((void**)&ffh,   g_ffh);
    cudaGetSymbolAddress((void**)&hidden,g_hidden);
    cudaGetSymbolAddress((void**)&logits,g_logits);
    cudaGetSymbolAddress((void**)&wqkvT, g_wqkvT);
    cudaGetSymbolAddress((void**)&woT,   g_woT);
    cudaGetSymbolAddress((void**)&wf1T,  g_wf1T);
    cudaGetSymbolAddress((void**)&wf2T,  g_wf2T);
    cudaGetSymbolAddress((void**)&bqkv,  g_bqkv);

    cudaFuncSetAttribute((const void*)hgemm<0,1,0,128>, cudaFuncAttributeMaxDynamicSharedMemorySize, HG_SMEM128);
    cudaFuncSetAttribute((const void*)hgemm<1,1,0,128>, cudaFuncAttributeMaxDynamicSharedMemorySize, HG_SMEM128);
    cudaFuncSetAttribute((const void*)hgemm<0,0,1,64>,  cudaFuncAttributeMaxDynamicSharedMemorySize, HG_SMEM64);
    cudaFuncSetAttribute((const void*)attn_kernel,      cudaFuncAttributeMaxDynamicSharedMemorySize, ATTN_SMEM);

    const int Mtok = B_ * S_;                    // 8192

    // weight prep
    {
        dim3 tb(32, 8);
        dim3 gHH(H_ / 32, H_ / 32, L_);
        transpose_cvt<<<gHH, tb>>>(Wq, wqkvT,                   H_, H_, (long)QKVN * H_);
        transpose_cvt<<<gHH, tb>>>(Wk, wqkvT + (size_t)H_*H_,   H_, H_, (long)QKVN * H_);
        transpose_cvt<<<gHH, tb>>>(Wv, wqkvT + (size_t)2*H_*H_, H_, H_, (long)QKVN * H_);
        transpose_cvt<<<gHH, tb>>>(Wo, woT, H_, H_, (long)H_ * H_);
        dim3 gF1(FF_ / 32, H_ / 32, L_);
        transpose_cvt<<<gF1, tb>>>(Wf1, wf1T, H_, FF_, (long)FF_ * H_);
        dim3 gF2(H_ / 32, FF_ / 32, L_);
        transpose_cvt<<<gF2, tb>>>(Wf2, wf2T, FF_, H_, (long)H_ * FF_);
        concat_bias<<<(L_ * QKVN + 255) / 256, 256>>>(bq, bk, bv, bqkv);
    }

    embed_kernel<<<Mtok / 8, 256>>>(src, seg, tib, we, pe, se, elng, elnb, sel, x, xh);

    dim3 gQKV(QKVN / 128, Mtok / 128);   // (18, 64)
    dim3 gH64(H_   / 64,  Mtok / 128);   // (12, 64) = 768 blocks
    dim3 gFF (FF_  / 128, Mtok / 128);   // (24, 64)
    dim3 gAtt(S_ / 128, B_ * NH_);       // (4, 192)

    for (int l = 0; l < L_; l++) {
        const __half* wqkv = wqkvT + (size_t)l * QKVN * H_;
        const __half* wo   = woT   + (size_t)l * H_ * H_;
        const __half* wf1  = wf1T  + (size_t)l * H_ * FF_;
        const __half* wf2  = wf2T  + (size_t)l * FF_ * H_;

        hgemm<0,1,0,128><<<gQKV, 256, HG_SMEM128>>>(xh, wqkv, bqkv + l * QKVN, qkv,
                                                    nullptr, H_, H_, H_, QKVN);
        attn_kernel<<<gAtt, 256, ATTN_SMEM>>>(qkv, seg, ctxh);
        // tmp = ctx @ Wo + bo + x  (residual fused), BN=64 for wave packing
        hgemm<0,0,1,64><<<gH64, 256, HG_SMEM64>>>(ctxh, wo, bo + l * H_, tmp, x,
                                                  H_, H_, H_, H_);
        ln_kernel<<<Mtok / 8, 256>>>(tmp, ln1g + l * H_, ln1b + l * H_, x, xh);

        hgemm<1,1,0,128><<<gFF, 256, HG_SMEM128>>>(xh, wf1, bf1 + l * FF_, ffh,
                                                   nullptr, H_, H_, H_, FF_);
        // tmp = gelu_ff @ Wf2 + bf2 + x  (residual fused), BN=64
        hgemm<0,0,1,64><<<gH64, 256, HG_SMEM64>>>(ffh, wf2, bf2 + l * H_, tmp, x,
                                                  FF_, FF_, FF_, H_);
        ln_kernel<<<Mtok / 8, 256>>>(tmp, ln2g + l * H_, ln2b + l * H_, x, xh);
    }

    dim3 gPool((H_ + 63) / 64, 1);
    gemm_kernel<2><<<gPool, 256>>>(x, Wp1, bp1, hidden, B_, H_, H_,
                                   S_ * H_, H_, H_);
    dim3 gCls(1, 1);
    gemm_kernel<0><<<gCls, 256>>>(hidden, Wp2, bp2, logits, B_, LAB_, H_,
                                  H_, LAB_, LAB_);

    loss_kernel<<<1, 32>>>(logits, tgt, (float*)d_out, out_size);
}

// round 11
// speedup vs baseline: 1.0903x; 1.0903x over previous
#include <cuda_runtime.h>
#include <cuda_fp16.h>
#include <math.h>
#include <stdint.h>

#define B_   16
#define S_   512
#define H_   768
#define NH_  12
#define L_   6
#define FF_  3072
#define DH_  64
#define LAB_ 10
#define QKVN 2304          // 3*H

// ---------------- scratch (device globals; no allocations allowed) ----------
__device__ float  g_x   [(size_t)B_*S_*H_];
__device__ __half g_xh  [(size_t)B_*S_*H_];
__device__ __half g_qkv [(size_t)B_*S_*QKVN];
__device__ __half g_ctxh[(size_t)B_*S_*H_];
__device__ float  g_tmp [(size_t)B_*S_*H_];
__device__ __half g_ffh [(size_t)B_*S_*FF_];
__device__ float  g_hidden[(size_t)B_*H_];
__device__ float  g_logits[(size_t)B_*LAB_];
// transposed + fp16 weights [N][K]
__device__ __half g_wqkvT[(size_t)L_*QKVN*H_];
__device__ __half g_woT  [(size_t)L_*H_*H_];
__device__ __half g_wf1T [(size_t)L_*FF_*H_];
__device__ __half g_wf2T [(size_t)L_*H_*FF_];
__device__ float  g_bqkv [(size_t)L_*QKVN];

// ---------------- small helpers ----------------
__device__ __forceinline__ uint32_t smem_u32(const void* p) {
    return (uint32_t)__cvta_generic_to_shared(p);
}

__device__ __forceinline__ void cp16s(uint32_t s, const void* g) {
    asm volatile("cp.async.ca.shared.global [%0], [%1], 16;\n" :: "r"(s), "l"(g));
}

__device__ __forceinline__ void ldsm4(uint32_t* r, uint32_t a) {
    asm volatile("ldmatrix.sync.aligned.m8n8.x4.shared.b16 {%0,%1,%2,%3}, [%4];"
                 : "=r"(r[0]), "=r"(r[1]), "=r"(r[2]), "=r"(r[3]) : "r"(a));
}

__device__ __forceinline__ void ldsm4t(uint32_t* r, uint32_t a) {
    asm volatile("ldmatrix.sync.aligned.m8n8.x4.trans.shared.b16 {%0,%1,%2,%3}, [%4];"
                 : "=r"(r[0]), "=r"(r[1]), "=r"(r[2]), "=r"(r[3]) : "r"(a));
}

__device__ __forceinline__ void mma_f16(float* c, const uint32_t* a, const uint32_t* b) {
    asm volatile(
        "mma.sync.aligned.m16n8k16.row.col.f32.f16.f16.f32 "
        "{%0,%1,%2,%3}, {%4,%5,%6,%7}, {%8,%9}, {%0,%1,%2,%3};\n"
        : "+f"(c[0]), "+f"(c[1]), "+f"(c[2]), "+f"(c[3])
        : "r"(a[0]), "r"(a[1]), "r"(a[2]), "r"(a[3]), "r"(b[0]), "r"(b[1]));
}

__device__ __forceinline__ float gelu_tanh(float v) {
    float c = v * v * v;
    return 0.5f * v * (1.f + tanhf(0.7978845608028654f * (v + 0.044715f * c)));
}

__device__ __forceinline__ float warp_sum(float v) {
    #pragma unroll
    for (int o = 16; o; o >>= 1) v += __shfl_xor_sync(0xffffffffu, v, o);
    return v;
}

__device__ __forceinline__ uint32_t pack2(float a, float b) {
    __half2 h = __floats2half2_rn(a, b);
    return *(uint32_t*)&h;
}

// ---------------- weight transpose + fp16 convert ----------------
__global__ void transpose_cvt(const float* __restrict__ in, __half* __restrict__ out,
                              int R, int C, long ozs)
{
    in  += (size_t)blockIdx.z * R * C;
    out += (size_t)blockIdx.z * ozs;
    __shared__ float t[32][33];
    int c0 = blockIdx.x * 32, r0 = blockIdx.y * 32;
    int tx = threadIdx.x, ty = threadIdx.y;
    #pragma unroll
    for (int i = 0; i < 32; i += 8)
        t[ty + i][tx] = in[(size_t)(r0 + ty + i) * C + c0 + tx];
    __syncthreads();
    #pragma unroll
    for (int i = 0; i < 32; i += 8)
        out[(size_t)(c0 + ty + i) * R + r0 + tx] = __float2half_rn(t[tx][ty + i]);
}

__global__ void concat_bias(const float* __restrict__ bq, const float* __restrict__ bk,
                            const float* __restrict__ bv, float* __restrict__ out)
{
    int i = blockIdx.x * 256 + threadIdx.x;
    if (i >= L_ * QKVN) return;
    int l = i / QKVN, r = i - l * QKVN;
    float val;
    if (r < H_)            val = bq[l * H_ + r];
    else if (r < 2 * H_)   val = bk[l * H_ + r - H_];
    else                   val = bv[l * H_ + r - 2 * H_];
    out[i] = val;
}

// ---------------- embedding + LN + selection (warp per token) ----------------
__global__ void embed_kernel(const int* __restrict__ src, const int* __restrict__ seg,
                             const int* __restrict__ tib,
                             const float* __restrict__ we, const float* __restrict__ pe,
                             const float* __restrict__ se,
                             const float* __restrict__ g, const float* __restrict__ bta,
                             const float* __restrict__ sel, float* __restrict__ x,
                             __half* __restrict__ xh)
{
    int t = blockIdx.x * 8 + (threadIdx.x >> 5);
    int lane = threadIdx.x & 31;
    int s = t % S_;
    int w = src[t], sg = seg[t];
    const float4* wr = (const float4*)(we + (size_t)w * H_);
    const float4* pr = (const float4*)(pe + (size_t)s * H_);
    const float4* sr = (const float4*)(se + (size_t)sg * H_);
    float4 v[6];
    float lsum = 0.f, lsq = 0.f;
    #pragma unroll
    for (int i = 0; i < 6; i++) {
        int idx = lane + 32 * i;
        float4 a = wr[idx], bv4 = pr[idx], c = sr[idx];
        v[i].x = a.x + bv4.x + c.x; v[i].y = a.y + bv4.y + c.y;
        v[i].z = a.z + bv4.z + c.z; v[i].w = a.w + bv4.w + c.w;
        lsum += v[i].x + v[i].y + v[i].z + v[i].w;
        lsq  += v[i].x*v[i].x + v[i].y*v[i].y + v[i].z*v[i].z + v[i].w*v[i].w;
    }
    float tot = warp_sum(lsum), totsq = warp_sum(lsq);
    float mean = tot / H_;
    float var  = totsq / H_ - mean * mean;
    float inv  = rsqrtf(var + 1e-5f);
    float f = sel[tib[t]];
    float4* xo = (float4*)(x + (size_t)t * H_);
    uint2*  xho = (uint2*)(xh + (size_t)t * H_);
    const float4* g4 = (const float4*)g;
    const float4* b4 = (const float4*)bta;
    #pragma unroll
    for (int i = 0; i < 6; i++) {
        int idx = lane + 32 * i;
        float4 gg = g4[idx], bb = b4[idx], o;
        o.x = ((v[i].x - mean) * inv * gg.x + bb.x) * f;
        o.y = ((v[i].y - mean) * inv * gg.y + bb.y) * f;
        o.z = ((v[i].z - mean) * inv * gg.z + bb.z) * f;
        o.w = ((v[i].w - mean) * inv * gg.w + bb.w) * f;
        xo[idx] = o;
        uint2 u; u.x = pack2(o.x, o.y); u.y = pack2(o.z, o.w);
        xho[idx] = u;
    }
}

// ---------------- LN over tmp (residual already fused in GEMM) --------------
__global__ void ln_kernel(const float* __restrict__ t,
                          const float* __restrict__ g, const float* __restrict__ bta,
                          float* __restrict__ x, __half* __restrict__ xh)
{
    int row = blockIdx.x * 8 + (threadIdx.x >> 5);
    int lane = threadIdx.x & 31;
    const float4* tr = (const float4*)(t + (size_t)row * H_);
    float4 v[6];
    float lsum = 0.f, lsq = 0.f;
    #pragma unroll
    for (int i = 0; i < 6; i++) {
        v[i] = tr[lane + 32 * i];
        lsum += v[i].x + v[i].y + v[i].z + v[i].w;
        lsq  += v[i].x*v[i].x + v[i].y*v[i].y + v[i].z*v[i].z + v[i].w*v[i].w;
    }
    float tot = warp_sum(lsum), totsq = warp_sum(lsq);
    float mean = tot / H_;
    float var  = totsq / H_ - mean * mean;
    float inv  = rsqrtf(var + 1e-5f);
    float4* xo = (float4*)(x + (size_t)row * H_);
    uint2*  xho = (uint2*)(xh + (size_t)row * H_);
    const float4* g4 = (const float4*)g;
    const float4* b4 = (const float4*)bta;
    #pragma unroll
    for (int i = 0; i < 6; i++) {
        int idx = lane + 32 * i;
        float4 gg = g4[idx], bb = b4[idx], o;
        o.x = (v[i].x - mean) * inv * gg.x + bb.x;
        o.y = (v[i].y - mean) * inv * gg.y + bb.y;
        o.z = (v[i].z - mean) * inv * gg.z + bb.z;
        o.w = (v[i].w - mean) * inv * gg.w + bb.w;
        xo[idx] = o;
        uint2 u; u.x = pack2(o.x, o.y); u.y = pack2(o.z, o.w);
        xho[idx] = u;
    }
}

// =====================================================================
// FP16 tensor-core GEMM (R9 config): BM=128, BN=128, BK=64, 256 threads,
// warp tile 32x64, m16n8k16, 3-stage cp.async, XOR-swizzled 128B rows,
// one __syncthreads per k-tile.
// ACT: 0 none, 1 gelu. OUTH: 1 half out, 0 float out. RES: add Res.
// =====================================================================
#define HG_SMEM 98304   // 3 stages * (16KB A + 16KB B)

template<int ACT, int OUTH, int RES>
__global__ void __launch_bounds__(256)
hgemm(const __half* __restrict__ A, const __half* __restrict__ Bw,
      const float* __restrict__ bias, void* __restrict__ Cout,
      const float* __restrict__ Res,
      int K, int lda, int ldb, int ldc)
{
    extern __shared__ char smem[];
    const uint32_t sb = smem_u32(smem);

    const int m0  = blockIdx.y * 128;
    const int n0  = blockIdx.x * 128;
    const int tid = threadIdx.x;
    const int lane = tid & 31, wid = tid >> 5;
    const int wm = wid & 3, wn = wid >> 2;
    const int g = lane >> 2, t = lane & 3;

    const int nt = K >> 6;     // BK = 64 halves = 128B rows

    auto load_st = [&](int kt) {
        int st = kt % 3;
        int k0 = kt << 6;
        uint32_t ab = sb + st * 32768;
        uint32_t bb = ab + 16384;
        #pragma unroll
        for (int i = 0; i < 4; i++) {
            int c = i * 256 + tid;              // 1024 chunks per operand
            int row = c >> 3, ch = c & 7;
            uint32_t d = ((uint32_t)row << 7) + (uint32_t)((ch ^ (row & 7)) << 4);
            cp16s(ab + d, A  + (size_t)(m0 + row) * lda + k0 + ch * 8);
            cp16s(bb + d, Bw + (size_t)(n0 + row) * ldb + k0 + ch * 8);
        }
        asm volatile("cp.async.commit_group;" ::: "memory");
    };

    float acc[2][8][4];
    #pragma unroll
    for (int i = 0; i < 2; i++)
        #pragma unroll
        for (int j = 0; j < 8; j++)
            #pragma unroll
            for (int r = 0; r < 4; r++) acc[i][j][r] = 0.f;

    load_st(0);
    if (nt > 1) load_st(1);

    const int arow_b = wm * 32 + (lane & 15);                       // + mt*16
    const int achk_b = (lane >> 4);                                 // + ks*2
    const int brow_b = wn * 64 + ((lane >> 4) << 3) + (lane & 7);   // + p*16
    const int bchk_b = ((lane >> 3) & 1);                           // + ks*2

    for (int kt = 0; kt < nt; kt++) {
        int st = kt % 3;
        if (kt + 1 < nt)
            asm volatile("cp.async.wait_group 1;" ::: "memory");
        else
            asm volatile("cp.async.wait_group 0;" ::: "memory");
        __syncthreads();
        if (kt + 2 < nt) load_st(kt + 2);

        uint32_t ab = sb + st * 32768;
        uint32_t bb = ab + 16384;

        #pragma unroll
        for (int ks = 0; ks < 4; ks++) {
            uint32_t afr[2][4];
            #pragma unroll
            for (int mt = 0; mt < 2; mt++) {
                int row = arow_b + mt * 16;
                int ch  = achk_b + ks * 2;
                ldsm4(afr[mt], ab + ((uint32_t)row << 7)
                                  + (uint32_t)((ch ^ (row & 7)) << 4));
            }
            uint32_t bfr[8][2];
            #pragma unroll
            for (int p = 0; p < 4; p++) {
                int row = brow_b + p * 16;
                int ch  = bchk_b + ks * 2;
                uint32_t rr[4];
                ldsm4(rr, bb + ((uint32_t)row << 7)
                             + (uint32_t)((ch ^ (row & 7)) << 4));
                bfr[2 * p][0]     = rr[0]; bfr[2 * p][1]     = rr[1];
                bfr[2 * p + 1][0] = rr[2]; bfr[2 * p + 1][1] = rr[3];
            }
            #pragma unroll
            for (int mt = 0; mt < 2; mt++)
                #pragma unroll
                for (int ntl = 0; ntl < 8; ntl++)
                    mma_f16(acc[mt][ntl], afr[mt], bfr[ntl]);
        }
    }

    #pragma unroll
    for (int mt = 0; mt < 2; mt++) {
        #pragma unroll
        for (int ntl = 0; ntl < 8; ntl++) {
            int row = m0 + wm * 32 + mt * 16 + g;
            int col = n0 + wn * 64 + ntl * 8 + t * 2;
            float bv0 = bias[col], bv1 = bias[col + 1];
            #pragma unroll
            for (int half_ = 0; half_ < 2; half_++) {
                int r = row + half_ * 8;
                float v0 = acc[mt][ntl][half_ * 2 + 0] + bv0;
                float v1 = acc[mt][ntl][half_ * 2 + 1] + bv1;
                if (ACT == 1) { v0 = gelu_tanh(v0); v1 = gelu_tanh(v1); }
                if (RES) {
                    float2 rr = *(const float2*)&Res[(size_t)r * ldc + col];
                    v0 += rr.x; v1 += rr.y;
                }
                if (OUTH) {
                    __half2* C = (__half2*)((__half*)Cout + (size_t)r * ldc + col);
                    *C = __floats2half2_rn(v0, v1);
                } else {
                    float* C = (float*)Cout + (size_t)r * ldc + col;
                    *(float2*)C = make_float2(v0, v1);
                }
            }
        }
    }
}

// =====================================================================
// Fused flash-attention: P fragments formed directly in registers
// (C-fragment of S == A-fragment of P up to half2 packing) — no smem
// round-trip, no syncwarp in the PV path.
// =====================================================================
#define ATTN_SMEM  ((128*72 + 2*64*72 + 2*64*72) * 2 + 512 * 4)   // 57344

__global__ void __launch_bounds__(256)
attn_kernel(const __half* __restrict__ qkv, const int* __restrict__ seg,
            __half* __restrict__ ctx)
{
    extern __shared__ __half hsm[];
    __half* sP    = hsm;                       // 128*72 (Q staging)
    __half* sK    = sP + 128 * 72;             // 2 * 64*72
    __half* sV    = sK + 2 * 64 * 72;          // 2 * 64*72
    float*  smask = (float*)(sV + 2 * 64 * 72);

    const int bh = blockIdx.y;
    const int b = bh / NH_, h = bh - b * NH_;
    const int q0 = blockIdx.x * 128;

    const __half* qp = qkv + (size_t)b * S_ * QKVN + h * DH_;
    const __half* kp = qp + H_;
    __half* cp = ctx + ((size_t)b * S_ + q0) * H_ + h * DH_;

    const int tid = threadIdx.x, lane = tid & 31, wid = tid >> 5;
    const int g = lane >> 2, t = lane & 3;
    const uint32_t sPb = smem_u32(sP);
    const uint32_t sKb0 = smem_u32(sK);
    const uint32_t sVb0 = smem_u32(sV);

    for (int i = tid; i < S_; i += 256)
        smask[i] = (seg[b * S_ + i] > 0) ? 0.f : -1e9f;

    #pragma unroll
    for (int i = 0; i < 4; i++) {
        int c = i * 256 + tid;
        int row = c >> 3, kc = (c & 7) << 3;
        cp16s(sPb + (uint32_t)row * 144 + ((c & 7) << 4),
              qp + (size_t)(q0 + row) * QKVN + kc);
    }
    asm volatile("cp.async.commit_group;" ::: "memory");
    asm volatile("cp.async.wait_group 0;" ::: "memory");
    __syncthreads();

    const uint32_t a_base = (uint32_t)(wid * 16 + (lane & 15)) * 144 + ((lane >> 4) << 4);
    uint32_t qf[4][4];
    #pragma unroll
    for (int s = 0; s < 4; s++)
        ldsm4(qf[s], sPb + a_base + s * 32);
    __syncthreads();

    auto load_kv = [&](int kt, int buf) {
        int kbase = kt * 64;
        #pragma unroll
        for (int i = 0; i < 2; i++) {
            int c = i * 256 + tid;
            int row = c >> 3, kc = (c & 7) << 3;
            const __half* kg = kp + (size_t)(kbase + row) * QKVN + kc;
            uint32_t d = (uint32_t)row * 144 + ((c & 7) << 4);
            cp16s(sKb0 + buf * 9216 + d, kg);
            cp16s(sVb0 + buf * 9216 + d, kg + H_);
        }
        asm volatile("cp.async.commit_group;" ::: "memory");
    };
    load_kv(0, 0);

    const uint32_t bK_base = (uint32_t)(((lane >> 4) << 3) + (lane & 7)) * 144
                           + (((lane >> 3) & 1) << 4);
    const uint32_t bV_base = (uint32_t)(lane & 15) * 144 + (((lane >> 4) & 1) << 4);

    float m_run[2] = {-1e30f, -1e30f};
    float l_run[2] = {0.f, 0.f};
    float o[8][4];
    #pragma unroll
    for (int ntl = 0; ntl < 8; ntl++)
        #pragma unroll
        for (int r = 0; r < 4; r++) o[ntl][r] = 0.f;

    for (int kt = 0; kt < S_ / 64; kt++) {
        int buf = kt & 1;
        asm volatile("cp.async.wait_group 0;" ::: "memory");
        __syncthreads();
        if (kt + 1 < S_ / 64) load_kv(kt + 1, buf ^ 1);

        uint32_t sKb = sKb0 + buf * 9216;
        uint32_t sVb = sVb0 + buf * 9216;

        // S = Q @ K^T
        float sacc[8][4];
        #pragma unroll
        for (int ntl = 0; ntl < 8; ntl++)
            #pragma unroll
            for (int r = 0; r < 4; r++) sacc[ntl][r] = 0.f;
        #pragma unroll
        for (int s = 0; s < 4; s++) {
            uint32_t bfr[8][2];
            #pragma unroll
            for (int p = 0; p < 4; p++) {
                uint32_t rr[4];
                ldsm4(rr, sKb + bK_base + p * (16 * 144) + s * 32);
                bfr[2 * p][0]     = rr[0]; bfr[2 * p][1]     = rr[1];
                bfr[2 * p + 1][0] = rr[2]; bfr[2 * p + 1][1] = rr[3];
            }
            #pragma unroll
            for (int ntl = 0; ntl < 8; ntl++)
                mma_f16(sacc[ntl], qf[s], bfr[ntl]);
        }

        // scale + mask + online softmax
        float tmax0 = -1e30f, tmax1 = -1e30f;
        #pragma unroll
        for (int ntl = 0; ntl < 8; ntl++) {
            int col = kt * 64 + ntl * 8 + t * 2;
            float mb0 = smask[col], mb1 = smask[col + 1];
            sacc[ntl][0] = fmaf(sacc[ntl][0], 0.125f, mb0);
            sacc[ntl][1] = fmaf(sacc[ntl][1], 0.125f, mb1);
            sacc[ntl][2] = fmaf(sacc[ntl][2], 0.125f, mb0);
            sacc[ntl][3] = fmaf(sacc[ntl][3], 0.125f, mb1);
            tmax0 = fmaxf(tmax0, fmaxf(sacc[ntl][0], sacc[ntl][1]));
            tmax1 = fmaxf(tmax1, fmaxf(sacc[ntl][2], sacc[ntl][3]));
        }
        tmax0 = fmaxf(tmax0, __shfl_xor_sync(0xffffffffu, tmax0, 1));
        tmax0 = fmaxf(tmax0, __shfl_xor_sync(0xffffffffu, tmax0, 2));
        tmax1 = fmaxf(tmax1, __shfl_xor_sync(0xffffffffu, tmax1, 1));
        tmax1 = fmaxf(tmax1, __shfl_xor_sync(0xffffffffu, tmax1, 2));
        float mnew0 = fmaxf(m_run[0], tmax0);
        float mnew1 = fmaxf(m_run[1], tmax1);
        float al0 = __expf(m_run[0] - mnew0);
        float al1 = __expf(m_run[1] - mnew1);
        float ts0 = 0.f, ts1 = 0.f;
        #pragma unroll
        for (int ntl = 0; ntl < 8; ntl++) {
            sacc[ntl][0] = __expf(sacc[ntl][0] - mnew0);
            sacc[ntl][1] = __expf(sacc[ntl][1] - mnew0);
            sacc[ntl][2] = __expf(sacc[ntl][2] - mnew1);
            sacc[ntl][3] = __expf(sacc[ntl][3] - mnew1);
            ts0 += sacc[ntl][0] + sacc[ntl][1];
            ts1 += sacc[ntl][2] + sacc[ntl][3];
        }
        ts0 += __shfl_xor_sync(0xffffffffu, ts0, 1);
        ts0 += __shfl_xor_sync(0xffffffffu, ts0, 2);
        ts1 += __shfl_xor_sync(0xffffffffu, ts1, 1);
        ts1 += __shfl_xor_sync(0xffffffffu, ts1, 2);
        l_run[0] = l_run[0] * al0 + ts0;
        l_run[1] = l_run[1] * al1 + ts1;
        m_run[0] = mnew0; m_run[1] = mnew1;
        #pragma unroll
        for (int ntl = 0; ntl < 8; ntl++) {
            o[ntl][0] *= al0; o[ntl][1] *= al0;
            o[ntl][2] *= al1; o[ntl][3] *= al1;
        }

        // P @ V : P fragments built directly from sacc registers.
        // pf[0]=P[g][16s+2t,+1], pf[1]=P[g+8][..], pf[2]=P[g][16s+8+2t,+1], pf[3]=P[g+8][..]
        #pragma unroll
        for (int s = 0; s < 4; s++) {
            uint32_t pf[4];
            pf[0] = pack2(sacc[2*s][0],   sacc[2*s][1]);
            pf[1] = pack2(sacc[2*s][2],   sacc[2*s][3]);
            pf[2] = pack2(sacc[2*s+1][0], sacc[2*s+1][1]);
            pf[3] = pack2(sacc[2*s+1][2], sacc[2*s+1][3]);
            uint32_t bfr[8][2];
            #pragma unroll
            for (int p = 0; p < 4; p++) {
                uint32_t rr[4];
                ldsm4t(rr, sVb + bV_base + s * (16 * 144) + p * 32);
                bfr[2 * p][0]     = rr[0]; bfr[2 * p][1]     = rr[1];
                bfr[2 * p + 1][0] = rr[2]; bfr[2 * p + 1][1] = rr[3];
            }
            #pragma unroll
            for (int ntl = 0; ntl < 8; ntl++)
                mma_f16(o[ntl], pf, bfr[ntl]);
        }
    }

    float rl0 = 1.f / l_run[0], rl1 = 1.f / l_run[1];
    int r0 = wid * 16 + g;
    #pragma unroll
    for (int ntl = 0; ntl < 8; ntl++) {
        int col = ntl * 8 + t * 2;
        *(__half2*)&cp[(size_t)r0 * H_ + col] =
            __floats2half2_rn(o[ntl][0] * rl0, o[ntl][1] * rl0);
        *(__half2*)&cp[(size_t)(r0 + 8) * H_ + col] =
            __floats2half2_rn(o[ntl][2] * rl1, o[ntl][3] * rl1);
    }
}

// ---------------- small SIMT GEMM (pooler + classifier only) ----------------
template<int ACT> // 0 none, 2 tanh
__global__ void gemm_kernel(const float* __restrict__ A, const float* __restrict__ Bm,
                            const float* __restrict__ bias, float* __restrict__ C,
                            int M, int N, int K, int lda, int ldb, int ldc)
{
    __shared__ float As[16][65];
    __shared__ float Bs[16][65];

    int m0 = blockIdx.y * 64;
    int n0 = blockIdx.x * 64;
    int tid = threadIdx.x;
    int tx = tid & 15, ty = tid >> 4;

    float acc[4][4] = {};

    for (int k0 = 0; k0 < K; k0 += 16) {
        #pragma unroll
        for (int i = tid; i < 64 * 16; i += 256) {
            int m = i >> 4, k = i & 15;
            int gm = m0 + m, gk = k0 + k;
            As[k][m] = (gm < M && gk < K) ? A[(long)gm * lda + gk] : 0.f;
        }
        #pragma unroll
        for (int i = tid; i < 16 * 64; i += 256) {
            int k = i >> 6, n = i & 63;
            int gk = k0 + k, gn = n0 + n;
            Bs[k][n] = (gk < K && gn < N) ? Bm[(long)gk * ldb + gn] : 0.f;
        }
        __syncthreads();
        #pragma unroll
        for (int k = 0; k < 16; k++) {
            float a[4], bb[4];
            #pragma unroll
            for (int i = 0; i < 4; i++) a[i] = As[k][ty * 4 + i];
            #pragma unroll
            for (int j = 0; j < 4; j++) bb[j] = Bs[k][tx * 4 + j];
            #pragma unroll
            for (int i = 0; i < 4; i++)
                #pragma unroll
                for (int j = 0; j < 4; j++)
                    acc[i][j] = fmaf(a[i], bb[j], acc[i][j]);
        }
        __syncthreads();
    }

    #pragma unroll
    for (int i = 0; i < 4; i++) {
        int gm = m0 + ty * 4 + i;
        if (gm >= M) continue;
        #pragma unroll
        for (int j = 0; j < 4; j++) {
            int gn = n0 + tx * 4 + j;
            if (gn >= N) continue;
            float v = acc[i][j];
            if (bias) v += bias[gn];
            if (ACT == 2) v = tanhf(v);
            C[(long)gm * ldc + gn] = v;
        }
    }
}

// ---------------- log-softmax + NLL loss + output write ----------------
__global__ void loss_kernel(const float* __restrict__ logits, const int* __restrict__ tgt,
                            float* __restrict__ out, int out_size)
{
    int lane = threadIdx.x;
    float lp = 0.f;
    if (lane < B_) {
        const float* row = logits + lane * LAB_;
        float mx = row[0];
        #pragma unroll
        for (int j = 1; j < LAB_; j++) mx = fmaxf(mx, row[j]);
        float s = 0.f;
        #pragma unroll
        for (int j = 0; j < LAB_; j++) s += expf(row[j] - mx);
        lp = row[tgt[lane]] - mx - logf(s);
    }
    #pragma unroll
    for (int o = 16; o; o >>= 1) lp += __shfl_down_sync(0xffffffffu, lp, o);
    int ofs = (out_size > B_ * LAB_) ? 1 : 0;
    if (lane == 0 && ofs) out[0] = -lp / (float)B_;
    for (int i = lane; i < B_ * LAB_; i += 32) out[ofs + i] = logits[i];
}

// ---------------- host launch ----------------
extern "C" void kernel_launch(void* const* d_in, const int* in_sizes, int n_in,
                              void* d_out, int out_size)
{
    const int*   src  = (const int*)d_in[0];
    const int*   seg  = (const int*)d_in[1];
    const int*   tgt  = (const int*)d_in[2];
    const int*   tib  = (const int*)d_in[3];
    const float* we   = (const float*)d_in[4];
    const float* pe   = (const float*)d_in[5];
    const float* se   = (const float*)d_in[6];
    const float* elng = (const float*)d_in[7];
    const float* elnb = (const float*)d_in[8];
    const float* Wq   = (const float*)d_in[9];
    const float* bq   = (const float*)d_in[10];
    const float* Wk   = (const float*)d_in[11];
    const float* bk   = (const float*)d_in[12];
    const float* Wv   = (const float*)d_in[13];
    const float* bv   = (const float*)d_in[14];
    const float* Wo   = (const float*)d_in[15];
    const float* bo   = (const float*)d_in[16];
    const float* ln1g = (const float*)d_in[17];
    const float* ln1b = (const float*)d_in[18];
    const float* Wf1  = (const float*)d_in[19];
    const float* bf1  = (const float*)d_in[20];
    const float* Wf2  = (const float*)d_in[21];
    const float* bf2  = (const float*)d_in[22];
    const float* ln2g = (const float*)d_in[23];
    const float* ln2b = (const float*)d_in[24];
    const float* Wp1  = (const float*)d_in[25];
    const float* bp1  = (const float*)d_in[26];
    const float* Wp2  = (const float*)d_in[27];
    const float* bp2  = (const float*)d_in[28];
    const float* sel  = (const float*)d_in[29];
    (void)in_sizes; (void)n_in;

    float *x, *tmp, *hidden, *logits, *bqkv;
    __half *xh, *qkv, *ctxh, *ffh, *wqkvT, *woT, *wf1T, *wf2T;
    cudaGetSymbolAddress((void**)&x,     g_x);
    cudaGetSymbolAddress((void**)&xh,    g_xh);
    cudaGetSymbolAddress((void**)&qkv,   g_qkv);
    cudaGetSymbolAddress((void**)&ctxh,  g_ctxh);
    cudaGetSymbolAddress((void**)&tmp,   g_tmp);
    cudaGetSymbolAddress((void**)&ffh,   g_ffh);
    cudaGetSymbolAddress((void**)&hidden,g_hidden);
    cudaGetSymbolAddress((void**)&logits,g_logits);
    cudaGetSymbolAddress((void**)&wqkvT, g_wqkvT);
    cudaGetSymbolAddress((void**)&woT,   g_woT);
    cudaGetSymbolAddress((void**)&wf1T,  g_wf1T);
    cudaGetSymbolAddress((void**)&wf2T,  g_wf2T);
    cudaGetSymbolAddress((void**)&bqkv,  g_bqkv);

    cudaFuncSetAttribute((const void*)hgemm<0,1,0>, cudaFuncAttributeMaxDynamicSharedMemorySize, HG_SMEM);
    cudaFuncSetAttribute((const void*)hgemm<0,0,1>, cudaFuncAttributeMaxDynamicSharedMemorySize, HG_SMEM);
    cudaFuncSetAttribute((const void*)hgemm<1,1,0>, cudaFuncAttributeMaxDynamicSharedMemorySize, HG_SMEM);
    cudaFuncSetAttribute((const void*)attn_kernel,  cudaFuncAttributeMaxDynamicSharedMemorySize, ATTN_SMEM);

    const int Mtok = B_ * S_;                    // 8192

    // weight prep
    {
        dim3 tb(32, 8);
        dim3 gHH(H_ / 32, H_ / 32, L_);
        transpose_cvt<<<gHH, tb>>>(Wq, wqkvT,                   H_, H_, (long)QKVN * H_);
        transpose_cvt<<<gHH, tb>>>(Wk, wqkvT + (size_t)H_*H_,   H_, H_, (long)QKVN * H_);
        transpose_cvt<<<gHH, tb>>>(Wv, wqkvT + (size_t)2*H_*H_, H_, H_, (long)QKVN * H_);
        transpose_cvt<<<gHH, tb>>>(Wo, woT, H_, H_, (long)H_ * H_);
        dim3 gF1(FF_ / 32, H_ / 32, L_);
        transpose_cvt<<<gF1, tb>>>(Wf1, wf1T, H_, FF_, (long)FF_ * H_);
        dim3 gF2(H_ / 32, FF_ / 32, L_);
        transpose_cvt<<<gF2, tb>>>(Wf2, wf2T, FF_, H_, (long)H_ * FF_);
        concat_bias<<<(L_ * QKVN + 255) / 256, 256>>>(bq, bk, bv, bqkv);
    }

    embed_kernel<<<Mtok / 8, 256>>>(src, seg, tib, we, pe, se, elng, elnb, sel, x, xh);

    dim3 gQKV(QKVN / 128, Mtok / 128);   // (18, 64)
    dim3 gH  (H_   / 128, Mtok / 128);   // (6, 64)
    dim3 gFF (FF_  / 128, Mtok / 128);   // (24, 64)
    dim3 gAtt(S_ / 128, B_ * NH_);       // (4, 192)

    for (int l = 0; l < L_; l++) {
        const __half* wqkv = wqkvT + (size_t)l * QKVN * H_;
        const __half* wo   = woT   + (size_t)l * H_ * H_;
        const __half* wf1  = wf1T  + (size_t)l * H_ * FF_;
        const __half* wf2  = wf2T  + (size_t)l * FF_ * H_;

        hgemm<0,1,0><<<gQKV, 256, HG_SMEM>>>(xh, wqkv, bqkv + l * QKVN, qkv, nullptr,
                                             H_, H_, H_, QKVN);
        attn_kernel<<<gAtt, 256, ATTN_SMEM>>>(qkv, seg, ctxh);
        // tmp = ctx @ Wo + bo + x  (residual fused)
        hgemm<0,0,1><<<gH, 256, HG_SMEM>>>(ctxh, wo, bo + l * H_, tmp, x,
                                           H_, H_, H_, H_);
        ln_kernel<<<Mtok / 8, 256>>>(tmp, ln1g + l * H_, ln1b + l * H_, x, xh);

        hgemm<1,1,0><<<gFF, 256, HG_SMEM>>>(xh, wf1, bf1 + l * FF_, ffh, nullptr,
                                            H_, H_, H_, FF_);
        // tmp = gelu_ff @ Wf2 + bf2 + x  (residual fused)
        hgemm<0,0,1><<<gH, 256, HG_SMEM>>>(ffh, wf2, bf2 + l * H_, tmp, x,
                                           FF_, FF_, FF_, H_);
        ln_kernel<<<Mtok / 8, 256>>>(tmp, ln2g + l * H_, ln2b + l * H_, x, xh);
    }

    dim3 gPool((H_ + 63) / 64, 1);
    gemm_kernel<2><<<gPool, 256>>>(x, Wp1, bp1, hidden, B_, H_, H_,
                                   S_ * H_, H_, H_);
    dim3 gCls(1, 1);
    gemm_kernel<0><<<gCls, 256>>>(hidden, Wp2, bp2, logits, B_, LAB_, H_,
                                  H_, LAB_, LAB_);

    loss_kernel<<<1, 32>>>(logits, tgt, (float*)d_out, out_size);
}

// round 12
// speedup vs baseline: 1.0907x; 1.0004x over previous
#include <cuda_runtime.h>
#include <cuda_fp16.h>
#include <math.h>
#include <stdint.h>

#define B_   16
#define S_   512
#define H_   768
#define NH_  12
#define L_   6
#define FF_  3072
#define DH_  64
#define LAB_ 10
#define QKVN 2304          // 3*H

// ---------------- scratch (device globals; no allocations allowed) ----------
__device__ float  g_x   [(size_t)B_*S_*H_];
__device__ __half g_xh  [(size_t)B_*S_*H_];
__device__ __half g_qkv [(size_t)B_*S_*QKVN];
__device__ __half g_ctxh[(size_t)B_*S_*H_];
__device__ float  g_tmp [(size_t)B_*S_*H_];
__device__ __half g_ffh [(size_t)B_*S_*FF_];
__device__ float  g_hidden[(size_t)B_*H_];
__device__ float  g_logits[(size_t)B_*LAB_];
// transposed + fp16 weights [N][K]
__device__ __half g_wqkvT[(size_t)L_*QKVN*H_];
__device__ __half g_woT  [(size_t)L_*H_*H_];
__device__ __half g_wf1T [(size_t)L_*FF_*H_];
__device__ __half g_wf2T [(size_t)L_*H_*FF_];
__device__ float  g_bqkv [(size_t)L_*QKVN];

// ---------------- small helpers ----------------
__device__ __forceinline__ uint32_t smem_u32(const void* p) {
    return (uint32_t)__cvta_generic_to_shared(p);
}

__device__ __forceinline__ void cp16s(uint32_t s, const void* g) {
    asm volatile("cp.async.ca.shared.global [%0], [%1], 16;\n" :: "r"(s), "l"(g));
}

__device__ __forceinline__ void ldsm4(uint32_t* r, uint32_t a) {
    asm volatile("ldmatrix.sync.aligned.m8n8.x4.shared.b16 {%0,%1,%2,%3}, [%4];"
                 : "=r"(r[0]), "=r"(r[1]), "=r"(r[2]), "=r"(r[3]) : "r"(a));
}

__device__ __forceinline__ void ldsm4t(uint32_t* r, uint32_t a) {
    asm volatile("ldmatrix.sync.aligned.m8n8.x4.trans.shared.b16 {%0,%1,%2,%3}, [%4];"
                 : "=r"(r[0]), "=r"(r[1]), "=r"(r[2]), "=r"(r[3]) : "r"(a));
}

__device__ __forceinline__ void mma_f16(float* c, const uint32_t* a, const uint32_t* b) {
    asm volatile(
        "mma.sync.aligned.m16n8k16.row.col.f32.f16.f16.f32 "
        "{%0,%1,%2,%3}, {%4,%5,%6,%7}, {%8,%9}, {%0,%1,%2,%3};\n"
        : "+f"(c[0]), "+f"(c[1]), "+f"(c[2]), "+f"(c[3])
        : "r"(a[0]), "r"(a[1]), "r"(a[2]), "r"(a[3]), "r"(b[0]), "r"(b[1]));
}

// gelu(tanh approx) via exact identity 0.5*v*(1+tanh(u)) = v / (1 + exp(-2u)).
// Uses MUFU-backed intrinsics regardless of compiler flags.
__device__ __forceinline__ float gelu_tanh(float v) {
    float u = 0.7978845608028654f * (v + 0.044715f * v * v * v);
    return __fdividef(v, 1.f + __expf(-2.f * u));
}

__device__ __forceinline__ float warp_sum(float v) {
    #pragma unroll
    for (int o = 16; o; o >>= 1) v += __shfl_xor_sync(0xffffffffu, v, o);
    return v;
}

__device__ __forceinline__ uint32_t pack2(float a, float b) {
    __half2 h = __floats2half2_rn(a, b);
    return *(uint32_t*)&h;
}

// ---------------- weight transpose + fp16 convert ----------------
__global__ void transpose_cvt(const float* __restrict__ in, __half* __restrict__ out,
                              int R, int C, long ozs)
{
    in  += (size_t)blockIdx.z * R * C;
    out += (size_t)blockIdx.z * ozs;
    __shared__ float t[32][33];
    int c0 = blockIdx.x * 32, r0 = blockIdx.y * 32;
    int tx = threadIdx.x, ty = threadIdx.y;
    #pragma unroll
    for (int i = 0; i < 32; i += 8)
        t[ty + i][tx] = in[(size_t)(r0 + ty + i) * C + c0 + tx];
    __syncthreads();
    #pragma unroll
    for (int i = 0; i < 32; i += 8)
        out[(size_t)(c0 + ty + i) * R + r0 + tx] = __float2half_rn(t[tx][ty + i]);
}

__global__ void concat_bias(const float* __restrict__ bq, const float* __restrict__ bk,
                            const float* __restrict__ bv, float* __restrict__ out)
{
    int i = blockIdx.x * 256 + threadIdx.x;
    if (i >= L_ * QKVN) return;
    int l = i / QKVN, r = i - l * QKVN;
    float val;
    if (r < H_)            val = bq[l * H_ + r];
    else if (r < 2 * H_)   val = bk[l * H_ + r - H_];
    else                   val = bv[l * H_ + r - 2 * H_];
    out[i] = val;
}

// ---------------- embedding + LN + selection (warp per token) ----------------
__global__ void embed_kernel(const int* __restrict__ src, const int* __restrict__ seg,
                             const int* __restrict__ tib,
                             const float* __restrict__ we, const float* __restrict__ pe,
                             const float* __restrict__ se,
                             const float* __restrict__ g, const float* __restrict__ bta,
                             const float* __restrict__ sel, float* __restrict__ x,
                             __half* __restrict__ xh)
{
    int t = blockIdx.x * 8 + (threadIdx.x >> 5);
    int lane = threadIdx.x & 31;
    int s = t % S_;
    int w = src[t], sg = seg[t];
    const float4* wr = (const float4*)(we + (size_t)w * H_);
    const float4* pr = (const float4*)(pe + (size_t)s * H_);
    const float4* sr = (const float4*)(se + (size_t)sg * H_);
    float4 v[6];
    float lsum = 0.f, lsq = 0.f;
    #pragma unroll
    for (int i = 0; i < 6; i++) {
        int idx = lane + 32 * i;
        float4 a = wr[idx], bv4 = pr[idx], c = sr[idx];
        v[i].x = a.x + bv4.x + c.x; v[i].y = a.y + bv4.y + c.y;
        v[i].z = a.z + bv4.z + c.z; v[i].w = a.w + bv4.w + c.w;
        lsum += v[i].x + v[i].y + v[i].z + v[i].w;
        lsq  += v[i].x*v[i].x + v[i].y*v[i].y + v[i].z*v[i].z + v[i].w*v[i].w;
    }
    float tot = warp_sum(lsum), totsq = warp_sum(lsq);
    float mean = tot / H_;
    float var  = totsq / H_ - mean * mean;
    float inv  = rsqrtf(var + 1e-5f);
    float f = sel[tib[t]];
    float4* xo = (float4*)(x + (size_t)t * H_);
    uint2*  xho = (uint2*)(xh + (size_t)t * H_);
    const float4* g4 = (const float4*)g;
    const float4* b4 = (const float4*)bta;
    #pragma unroll
    for (int i = 0; i < 6; i++) {
        int idx = lane + 32 * i;
        float4 gg = g4[idx], bb = b4[idx], o;
        o.x = ((v[i].x - mean) * inv * gg.x + bb.x) * f;
        o.y = ((v[i].y - mean) * inv * gg.y + bb.y) * f;
        o.z = ((v[i].z - mean) * inv * gg.z + bb.z) * f;
        o.w = ((v[i].w - mean) * inv * gg.w + bb.w) * f;
        xo[idx] = o;
        uint2 u; u.x = pack2(o.x, o.y); u.y = pack2(o.z, o.w);
        xho[idx] = u;
    }
}

// ---------------- LN over tmp (residual already fused in GEMM) --------------
__global__ void ln_kernel(const float* __restrict__ t,
                          const float* __restrict__ g, const float* __restrict__ bta,
                          float* __restrict__ x, __half* __restrict__ xh)
{
    int row = blockIdx.x * 8 + (threadIdx.x >> 5);
    int lane = threadIdx.x & 31;
    const float4* tr = (const float4*)(t + (size_t)row * H_);
    float4 v[6];
    float lsum = 0.f, lsq = 0.f;
    #pragma unroll
    for (int i = 0; i < 6; i++) {
        v[i] = tr[lane + 32 * i];
        lsum += v[i].x + v[i].y + v[i].z + v[i].w;
        lsq  += v[i].x*v[i].x + v[i].y*v[i].y + v[i].z*v[i].z + v[i].w*v[i].w;
    }
    float tot = warp_sum(lsum), totsq = warp_sum(lsq);
    float mean = tot / H_;
    float var  = totsq / H_ - mean * mean;
    float inv  = rsqrtf(var + 1e-5f);
    float4* xo = (float4*)(x + (size_t)row * H_);
    uint2*  xho = (uint2*)(xh + (size_t)row * H_);
    const float4* g4 = (const float4*)g;
    const float4* b4 = (const float4*)bta;
    #pragma unroll
    for (int i = 0; i < 6; i++) {
        int idx = lane + 32 * i;
        float4 gg = g4[idx], bb = b4[idx], o;
        o.x = (v[i].x - mean) * inv * gg.x + bb.x;
        o.y = (v[i].y - mean) * inv * gg.y + bb.y;
        o.z = (v[i].z - mean) * inv * gg.z + bb.z;
        o.w = (v[i].w - mean) * inv * gg.w + bb.w;
        xo[idx] = o;
        uint2 u; u.x = pack2(o.x, o.y); u.y = pack2(o.z, o.w);
        xho[idx] = u;
    }
}

// =====================================================================
// FP16 tensor-core GEMM (R9 config): BM=128, BN=128, BK=64, 256 threads,
// warp tile 32x64, m16n8k16, 3-stage cp.async, XOR-swizzled 128B rows,
// one __syncthreads per k-tile.
// ACT: 0 none, 1 gelu. OUTH: 1 half out, 0 float out. RES: add Res.
// =====================================================================
#define HG_SMEM 98304   // 3 stages * (16KB A + 16KB B)

template<int ACT, int OUTH, int RES>
__global__ void __launch_bounds__(256)
hgemm(const __half* __restrict__ A, const __half* __restrict__ Bw,
      const float* __restrict__ bias, void* __restrict__ Cout,
      const float* __restrict__ Res,
      int K, int lda, int ldb, int ldc)
{
    extern __shared__ char smem[];
    const uint32_t sb = smem_u32(smem);

    const int m0  = blockIdx.y * 128;
    const int n0  = blockIdx.x * 128;
    const int tid = threadIdx.x;
    const int lane = tid & 31, wid = tid >> 5;
    const int wm = wid & 3, wn = wid >> 2;
    const int g = lane >> 2, t = lane & 3;

    const int nt = K >> 6;     // BK = 64 halves = 128B rows

    auto load_st = [&](int kt) {
        int st = kt % 3;
        int k0 = kt << 6;
        uint32_t ab = sb + st * 32768;
        uint32_t bb = ab + 16384;
        #pragma unroll
        for (int i = 0; i < 4; i++) {
            int c = i * 256 + tid;              // 1024 chunks per operand
            int row = c >> 3, ch = c & 7;
            uint32_t d = ((uint32_t)row << 7) + (uint32_t)((ch ^ (row & 7)) << 4);
            cp16s(ab + d, A  + (size_t)(m0 + row) * lda + k0 + ch * 8);
            cp16s(bb + d, Bw + (size_t)(n0 + row) * ldb + k0 + ch * 8);
        }
        asm volatile("cp.async.commit_group;" ::: "memory");
    };

    float acc[2][8][4];
    #pragma unroll
    for (int i = 0; i < 2; i++)
        #pragma unroll
        for (int j = 0; j < 8; j++)
            #pragma unroll
            for (int r = 0; r < 4; r++) acc[i][j][r] = 0.f;

    load_st(0);
    if (nt > 1) load_st(1);

    const int arow_b = wm * 32 + (lane & 15);                       // + mt*16
    const int achk_b = (lane >> 4);                                 // + ks*2
    const int brow_b = wn * 64 + ((lane >> 4) << 3) + (lane & 7);   // + p*16
    const int bchk_b = ((lane >> 3) & 1);                           // + ks*2

    for (int kt = 0; kt < nt; kt++) {
        int st = kt % 3;
        if (kt + 1 < nt)
            asm volatile("cp.async.wait_group 1;" ::: "memory");
        else
            asm volatile("cp.async.wait_group 0;" ::: "memory");
        __syncthreads();
        if (kt + 2 < nt) load_st(kt + 2);

        uint32_t ab = sb + st * 32768;
        uint32_t bb = ab + 16384;

        #pragma unroll
        for (int ks = 0; ks < 4; ks++) {
            uint32_t afr[2][4];
            #pragma unroll
            for (int mt = 0; mt < 2; mt++) {
                int row = arow_b + mt * 16;
                int ch  = achk_b + ks * 2;
                ldsm4(afr[mt], ab + ((uint32_t)row << 7)
                                  + (uint32_t)((ch ^ (row & 7)) << 4));
            }
            uint32_t bfr[8][2];
            #pragma unroll
            for (int p = 0; p < 4; p++) {
                int row = brow_b + p * 16;
                int ch  = bchk_b + ks * 2;
                uint32_t rr[4];
                ldsm4(rr, bb + ((uint32_t)row << 7)
                             + (uint32_t)((ch ^ (row & 7)) << 4));
                bfr[2 * p][0]     = rr[0]; bfr[2 * p][1]     = rr[1];
                bfr[2 * p + 1][0] = rr[2]; bfr[2 * p + 1][1] = rr[3];
            }
            #pragma unroll
            for (int mt = 0; mt < 2; mt++)
                #pragma unroll
                for (int ntl = 0; ntl < 8; ntl++)
                    mma_f16(acc[mt][ntl], afr[mt], bfr[ntl]);
        }
    }

    #pragma unroll
    for (int mt = 0; mt < 2; mt++) {
        #pragma unroll
        for (int ntl = 0; ntl < 8; ntl++) {
            int row = m0 + wm * 32 + mt * 16 + g;
            int col = n0 + wn * 64 + ntl * 8 + t * 2;
            float2 bv = *(const float2*)&bias[col];
            #pragma unroll
            for (int half_ = 0; half_ < 2; half_++) {
                int r = row + half_ * 8;
                float v0 = acc[mt][ntl][half_ * 2 + 0] + bv.x;
                float v1 = acc[mt][ntl][half_ * 2 + 1] + bv.y;
                if (ACT == 1) { v0 = gelu_tanh(v0); v1 = gelu_tanh(v1); }
                if (RES) {
                    float2 rr = *(const float2*)&Res[(size_t)r * ldc + col];
                    v0 += rr.x; v1 += rr.y;
                }
                if (OUTH) {
                    __half2* C = (__half2*)((__half*)Cout + (size_t)r * ldc + col);
                    *C = __floats2half2_rn(v0, v1);
                } else {
                    float* C = (float*)Cout + (size_t)r * ldc + col;
                    *(float2*)C = make_float2(v0, v1);
                }
            }
        }
    }
}

// =====================================================================
// Fused flash-attention: P fragments formed directly in registers.
// =====================================================================
#define ATTN_SMEM  ((128*72 + 2*64*72 + 2*64*72) * 2 + 512 * 4)   // 57344

__global__ void __launch_bounds__(256)
attn_kernel(const __half* __restrict__ qkv, const int* __restrict__ seg,
            __half* __restrict__ ctx)
{
    extern __shared__ __half hsm[];
    __half* sP    = hsm;                       // 128*72 (Q staging)
    __half* sK    = sP + 128 * 72;             // 2 * 64*72
    __half* sV    = sK + 2 * 64 * 72;          // 2 * 64*72
    float*  smask = (float*)(sV + 2 * 64 * 72);

    const int bh = blockIdx.y;
    const int b = bh / NH_, h = bh - b * NH_;
    const int q0 = blockIdx.x * 128;

    const __half* qp = qkv + (size_t)b * S_ * QKVN + h * DH_;
    const __half* kp = qp + H_;
    __half* cp = ctx + ((size_t)b * S_ + q0) * H_ + h * DH_;

    const int tid = threadIdx.x, lane = tid & 31, wid = tid >> 5;
    const int g = lane >> 2, t = lane & 3;
    const uint32_t sPb = smem_u32(sP);
    const uint32_t sKb0 = smem_u32(sK);
    const uint32_t sVb0 = smem_u32(sV);

    for (int i = tid; i < S_; i += 256)
        smask[i] = (seg[b * S_ + i] > 0) ? 0.f : -1e9f;

    #pragma unroll
    for (int i = 0; i < 4; i++) {
        int c = i * 256 + tid;
        int row = c >> 3, kc = (c & 7) << 3;
        cp16s(sPb + (uint32_t)row * 144 + ((c & 7) << 4),
              qp + (size_t)(q0 + row) * QKVN + kc);
    }
    asm volatile("cp.async.commit_group;" ::: "memory");
    asm volatile("cp.async.wait_group 0;" ::: "memory");
    __syncthreads();

    const uint32_t a_base = (uint32_t)(wid * 16 + (lane & 15)) * 144 + ((lane >> 4) << 4);
    uint32_t qf[4][4];
    #pragma unroll
    for (int s = 0; s < 4; s++)
        ldsm4(qf[s], sPb + a_base + s * 32);
    __syncthreads();

    auto load_kv = [&](int kt, int buf) {
        int kbase = kt * 64;
        #pragma unroll
        for (int i = 0; i < 2; i++) {
            int c = i * 256 + tid;
            int row = c >> 3, kc = (c & 7) << 3;
            const __half* kg = kp + (size_t)(kbase + row) * QKVN + kc;
            uint32_t d = (uint32_t)row * 144 + ((c & 7) << 4);
            cp16s(sKb0 + buf * 9216 + d, kg);
            cp16s(sVb0 + buf * 9216 + d, kg + H_);
        }
        asm volatile("cp.async.commit_group;" ::: "memory");
    };
    load_kv(0, 0);

    const uint32_t bK_base = (uint32_t)(((lane >> 4) << 3) + (lane & 7)) * 144
                           + (((lane >> 3) & 1) << 4);
    const uint32_t bV_base = (uint32_t)(lane & 15) * 144 + (((lane >> 4) & 1) << 4);

    float m_run[2] = {-1e30f, -1e30f};
    float l_run[2] = {0.f, 0.f};
    float o[8][4];
    #pragma unroll
    for (int ntl = 0; ntl < 8; ntl++)
        #pragma unroll
        for (int r = 0; r < 4; r++) o[ntl][r] = 0.f;

    for (int kt = 0; kt < S_ / 64; kt++) {
        int buf = kt & 1;
        asm volatile("cp.async.wait_group 0;" ::: "memory");
        __syncthreads();
        if (kt + 1 < S_ / 64) load_kv(kt + 1, buf ^ 1);

        uint32_t sKb = sKb0 + buf * 9216;
        uint32_t sVb = sVb0 + buf * 9216;

        // S = Q @ K^T
        float sacc[8][4];
        #pragma unroll
        for (int ntl = 0; ntl < 8; ntl++)
            #pragma unroll
            for (int r = 0; r < 4; r++) sacc[ntl][r] = 0.f;
        #pragma unroll
        for (int s = 0; s < 4; s++) {
            uint32_t bfr[8][2];
            #pragma unroll
            for (int p = 0; p < 4; p++) {
                uint32_t rr[4];
                ldsm4(rr, sKb + bK_base + p * (16 * 144) + s * 32);
                bfr[2 * p][0]     = rr[0]; bfr[2 * p][1]     = rr[1];
                bfr[2 * p + 1][0] = rr[2]; bfr[2 * p + 1][1] = rr[3];
            }
            #pragma unroll
            for (int ntl = 0; ntl < 8; ntl++)
                mma_f16(sacc[ntl], qf[s], bfr[ntl]);
        }

        // scale + mask + online softmax
        float tmax0 = -1e30f, tmax1 = -1e30f;
        #pragma unroll
        for (int ntl = 0; ntl < 8; ntl++) {
            int col = kt * 64 + ntl * 8 + t * 2;
            float mb0 = smask[col], mb1 = smask[col + 1];
            sacc[ntl][0] = fmaf(sacc[ntl][0], 0.125f, mb0);
            sacc[ntl][1] = fmaf(sacc[ntl][1], 0.125f, mb1);
            sacc[ntl][2] = fmaf(sacc[ntl][2], 0.125f, mb0);
            sacc[ntl][3] = fmaf(sacc[ntl][3], 0.125f, mb1);
            tmax0 = fmaxf(tmax0, fmaxf(sacc[ntl][0], sacc[ntl][1]));
            tmax1 = fmaxf(tmax1, fmaxf(sacc[ntl][2], sacc[ntl][3]));
        }
        tmax0 = fmaxf(tmax0, __shfl_xor_sync(0xffffffffu, tmax0, 1));
        tmax0 = fmaxf(tmax0, __shfl_xor_sync(0xffffffffu, tmax0, 2));
        tmax1 = fmaxf(tmax1, __shfl_xor_sync(0xffffffffu, tmax1, 1));
        tmax1 = fmaxf(tmax1, __shfl_xor_sync(0xffffffffu, tmax1, 2));
        float mnew0 = fmaxf(m_run[0], tmax0);
        float mnew1 = fmaxf(m_run[1], tmax1);
        float al0 = __expf(m_run[0] - mnew0);
        float al1 = __expf(m_run[1] - mnew1);
        float ts0 = 0.f, ts1 = 0.f;
        #pragma unroll
        for (int ntl = 0; ntl < 8; ntl++) {
            sacc[ntl][0] = __expf(sacc[ntl][0] - mnew0);
            sacc[ntl][1] = __expf(sacc[ntl][1] - mnew0);
            sacc[ntl][2] = __expf(sacc[ntl][2] - mnew1);
            sacc[ntl][3] = __expf(sacc[ntl][3] - mnew1);
            ts0 += sacc[ntl][0] + sacc[ntl][1];
            ts1 += sacc[ntl][2] + sacc[ntl][3];
        }
        ts0 += __shfl_xor_sync(0xffffffffu, ts0, 1);
        ts0 += __shfl_xor_sync(0xffffffffu, ts0, 2);
        ts1 += __shfl_xor_sync(0xffffffffu, ts1, 1);
        ts1 += __shfl_xor_sync(0xffffffffu, ts1, 2);
        l_run[0] = l_run[0] * al0 + ts0;
        l_run[1] = l_run[1] * al1 + ts1;
        m_run[0] = mnew0; m_run[1] = mnew1;
        #pragma unroll
        for (int ntl = 0; ntl < 8; ntl++) {
            o[ntl][0] *= al0; o[ntl][1] *= al0;
            o[ntl][2] *= al1; o[ntl][3] *= al1;
        }

        // P @ V : P fragments built directly from sacc registers.
        #pragma unroll
        for (int s = 0; s < 4; s++) {
            uint32_t pf[4];
            pf[0] = pack2(sacc[2*s][0],   sacc[2*s][1]);
            pf[1] = pack2(sacc[2*s][2],   sacc[2*s][3]);
            pf[2] = pack2(sacc[2*s+1][0], sacc[2*s+1][1]);
            pf[3] = pack2(sacc[2*s+1][2], sacc[2*s+1][3]);
            uint32_t bfr[8][2];
            #pragma unroll
            for (int p = 0; p < 4; p++) {
                uint32_t rr[4];
                ldsm4t(rr, sVb + bV_base + s * (16 * 144) + p * 32);
                bfr[2 * p][0]     = rr[0]; bfr[2 * p][1]     = rr[1];
                bfr[2 * p + 1][0] = rr[2]; bfr[2 * p + 1][1] = rr[3];
            }
            #pragma unroll
            for (int ntl = 0; ntl < 8; ntl++)
                mma_f16(o[ntl], pf, bfr[ntl]);
        }
    }

    float rl0 = 1.f / l_run[0], rl1 = 1.f / l_run[1];
    int r0 = wid * 16 + g;
    #pragma unroll
    for (int ntl = 0; ntl < 8; ntl++) {
        int col = ntl * 8 + t * 2;
        *(__half2*)&cp[(size_t)r0 * H_ + col] =
            __floats2half2_rn(o[ntl][0] * rl0, o[ntl][1] * rl0);
        *(__half2*)&cp[(size_t)(r0 + 8) * H_ + col] =
            __floats2half2_rn(o[ntl][2] * rl1, o[ntl][3] * rl1);
    }
}

// ---------------- small SIMT GEMM (pooler + classifier only) ----------------
template<int ACT> // 0 none, 2 tanh
__global__ void gemm_kernel(const float* __restrict__ A, const float* __restrict__ Bm,
                            const float* __restrict__ bias, float* __restrict__ C,
                            int M, int N, int K, int lda, int ldb, int ldc)
{
    __shared__ float As[16][65];
    __shared__ float Bs[16][65];

    int m0 = blockIdx.y * 64;
    int n0 = blockIdx.x * 64;
    int tid = threadIdx.x;
    int tx = tid & 15, ty = tid >> 4;

    float acc[4][4] = {};

    for (int k0 = 0; k0 < K; k0 += 16) {
        #pragma unroll
        for (int i = tid; i < 64 * 16; i += 256) {
            int m = i >> 4, k = i & 15;
            int gm = m0 + m, gk = k0 + k;
            As[k][m] = (gm < M && gk < K) ? A[(long)gm * lda + gk] : 0.f;
        }
        #pragma unroll
        for (int i = tid; i < 16 * 64; i += 256) {
            int k = i >> 6, n = i & 63;
            int gk = k0 + k, gn = n0 + n;
            Bs[k][n] = (gk < K && gn < N) ? Bm[(long)gk * ldb + gn] : 0.f;
        }
        __syncthreads();
        #pragma unroll
        for (int k = 0; k < 16; k++) {
            float a[4], bb[4];
            #pragma unroll
            for (int i = 0; i < 4; i++) a[i] = As[k][ty * 4 + i];
            #pragma unroll
            for (int j = 0; j < 4; j++) bb[j] = Bs[k][tx * 4 + j];
            #pragma unroll
            for (int i = 0; i < 4; i++)
                #pragma unroll
                for (int j = 0; j < 4; j++)
                    acc[i][j] = fmaf(a[i], bb[j], acc[i][j]);
        }
        __syncthreads();
    }

    #pragma unroll
    for (int i = 0; i < 4; i++) {
        int gm = m0 + ty * 4 + i;
        if (gm >= M) continue;
        #pragma unroll
        for (int j = 0; j < 4; j++) {
            int gn = n0 + tx * 4 + j;
            if (gn >= N) continue;
            float v = acc[i][j];
            if (bias) v += bias[gn];
            if (ACT == 2) v = tanhf(v);
            C[(long)gm * ldc + gn] = v;
        }
    }
}

// ---------------- log-softmax + NLL loss + output write ----------------
__global__ void loss_kernel(const float* __restrict__ logits, const int* __restrict__ tgt,
                            float* __restrict__ out, int out_size)
{
    int lane = threadIdx.x;
    float lp = 0.f;
    if (lane < B_) {
        const float* row = logits + lane * LAB_;
        float mx = row[0];
        #pragma unroll
        for (int j = 1; j < LAB_; j++) mx = fmaxf(mx, row[j]);
        float s = 0.f;
        #pragma unroll
        for (int j = 0; j < LAB_; j++) s += expf(row[j] - mx);
        lp = row[tgt[lane]] - mx - logf(s);
    }
    #pragma unroll
    for (int o = 16; o; o >>= 1) lp += __shfl_down_sync(0xffffffffu, lp, o);
    int ofs = (out_size > B_ * LAB_) ? 1 : 0;
    if (lane == 0 && ofs) out[0] = -lp / (float)B_;
    for (int i = lane; i < B_ * LAB_; i += 32) out[ofs + i] = logits[i];
}

// ---------------- host launch ----------------
extern "C" void kernel_launch(void* const* d_in, const int* in_sizes, int n_in,
                              void* d_out, int out_size)
{
    const int*   src  = (const int*)d_in[0];
    const int*   seg  = (const int*)d_in[1];
    const int*   tgt  = (const int*)d_in[2];
    const int*   tib  = (const int*)d_in[3];
    const float* we   = (const float*)d_in[4];
    const float* pe   = (const float*)d_in[5];
    const float* se   = (const float*)d_in[6];
    const float* elng = (const float*)d_in[7];
    const float* elnb = (const float*)d_in[8];
    const float* Wq   = (const float*)d_in[9];
    const float* bq   = (const float*)d_in[10];
    const float* Wk   = (const float*)d_in[11];
    const float* bk   = (const float*)d_in[12];
    const float* Wv   = (const float*)d_in[13];
    const float* bv   = (const float*)d_in[14];
    const float* Wo   = (const float*)d_in[15];
    const float* bo   = (const float*)d_in[16];
    const float* ln1g = (const float*)d_in[17];
    const float* ln1b = (const float*)d_in[18];
    const float* Wf1  = (const float*)d_in[19];
    const float* bf1  = (const float*)d_in[20];
    const float* Wf2  = (const float*)d_in[21];
    const float* bf2  = (const float*)d_in[22];
    const float* ln2g = (const float*)d_in[23];
    const float* ln2b = (const float*)d_in[24];
    const float* Wp1  = (const float*)d_in[25];
    const float* bp1  = (const float*)d_in[26];
    const float* Wp2  = (const float*)d_in[27];
    const float* bp2  = (const float*)d_in[28];
    const float* sel  = (const float*)d_in[29];
    (void)in_sizes; (void)n_in;

    float *x, *tmp, *hidden, *logits, *bqkv;
    __half *xh, *qkv, *ctxh, *ffh, *wqkvT, *woT, *wf1T, *wf2T;
    cudaGetSymbolAddress((void**)&x,     g_x);
    cudaGetSymbolAddress((void**)&xh,    g_xh);
    cudaGetSymbolAddress((void**)&qkv,   g_qkv);
    cudaGetSymbolAddress((void**)&ctxh,  g_ctxh);
    cudaGetSymbolAddress((void**)&tmp,   g_tmp);
    cudaGetSymbolAddress((void**)&ffh,   g_ffh);
    cudaGetSymbolAddress((void**)&hidden,g_hidden);
    cudaGetSymbolAddress((void**)&logits,g_logits);
    cudaGetSymbolAddress((void**)&wqkvT, g_wqkvT);
    cudaGetSymbolAddress((void**)&woT,   g_woT);
    cudaGetSymbolAddress((void**)&wf1T,  g_wf1T);
    cudaGetSymbolAddress((void**)&wf2T,  g_wf2T);
    cudaGetSymbolAddress((void**)&bqkv,  g_bqkv);

    cudaFuncSetAttribute((const void*)hgemm<0,1,0>, cudaFuncAttributeMaxDynamicSharedMemorySize, HG_SMEM);
    cudaFuncSetAttribute((const void*)hgemm<0,0,1>, cudaFuncAttributeMaxDynamicSharedMemorySize, HG_SMEM);
    cudaFuncSetAttribute((const void*)hgemm<1,1,0>, cudaFuncAttributeMaxDynamicSharedMemorySize, HG_SMEM);
    cudaFuncSetAttribute((const void*)attn_kernel,  cudaFuncAttributeMaxDynamicSharedMemorySize, ATTN_SMEM);

    const int Mtok = B_ * S_;                    // 8192

    // weight prep
    {
        dim3 tb(32, 8);
        dim3 gHH(H_ / 32, H_ / 32, L_);
        transpose_cvt<<<gHH, tb>>>(Wq, wqkvT,                   H_, H_, (long)QKVN * H_);
        transpose_cvt<<<gHH, tb>>>(Wk, wqkvT + (size_t)H_*H_,   H_, H_, (long)QKVN * H_);
        transpose_cvt<<<gHH, tb>>>(Wv, wqkvT + (size_t)2*H_*H_, H_, H_, (long)QKVN * H_);
        transpose_cvt<<<gHH, tb>>>(Wo, woT, H_, H_, (long)H_ * H_);
        dim3 gF1(FF_ / 32, H_ / 32, L_);
        transpose_cvt<<<gF1, tb>>>(Wf1, wf1T, H_, FF_, (long)FF_ * H_);
        dim3 gF2(H_ / 32, FF_ / 32, L_);
        transpose_cvt<<<gF2, tb>>>(Wf2, wf2T, FF_, H_, (long)H_ * FF_);
        concat_bias<<<(L_ * QKVN + 255) / 256, 256>>>(bq, bk, bv, bqkv);
    }

    embed_kernel<<<Mtok / 8, 256>>>(src, seg, tib, we, pe, se, elng, elnb, sel, x, xh);

    dim3 gQKV(QKVN / 128, Mtok / 128);   // (18, 64)
    dim3 gH  (H_   / 128, Mtok / 128);   // (6, 64)
    dim3 gFF (FF_  / 128, Mtok / 128);   // (24, 64)
    dim3 gAtt(S_ / 128, B_ * NH_);       // (4, 192)

    for (int l = 0; l < L_; l++) {
        const __half* wqkv = wqkvT + (size_t)l * QKVN * H_;
        const __half* wo   = woT   + (size_t)l * H_ * H_;
        const __half* wf1  = wf1T  + (size_t)l * H_ * FF_;
        const __half* wf2  = wf2T  + (size_t)l * FF_ * H_;

        hgemm<0,1,0><<<gQKV, 256, HG_SMEM>>>(xh, wqkv, bqkv + l * QKVN, qkv, nullptr,
                                             H_, H_, H_, QKVN);
        attn_kernel<<<gAtt, 256, ATTN_SMEM>>>(qkv, seg, ctxh);
        // tmp = ctx @ Wo + bo + x  (residual fused)
        hgemm<0,0,1><<<gH, 256, HG_SMEM>>>(ctxh, wo, bo + l * H_, tmp, x,
                                           H_, H_, H_, H_);
        ln_kernel<<<Mtok / 8, 256>>>(tmp, ln1g + l * H_, ln1b + l * H_, x, xh);

        hgemm<1,1,0><<<gFF, 256, HG_SMEM>>>(xh, wf1, bf1 + l * FF_, ffh, nullptr,
                                            H_, H_, H_, FF_);
        // tmp = gelu_ff @ Wf2 + bf2 + x  (residual fused)
        hgemm<0,0,1><<<gH, 256, HG_SMEM>>>(ffh, wf2, bf2 + l * H_, tmp, x,
                                           FF_, FF_, FF_, H_);
        ln_kernel<<<Mtok / 8, 256>>>(tmp, ln2g + l * H_, ln2b + l * H_, x, xh);
    }

    dim3 gPool((H_ + 63) / 64, 1);
    gemm_kernel<2><<<gPool, 256>>>(x, Wp1, bp1, hidden, B_, H_, H_,
                                   S_ * H_, H_, H_);
    dim3 gCls(1, 1);
    gemm_kernel<0><<<gCls, 256>>>(hidden, Wp2, bp2, logits, B_, LAB_, H_,
                                  H_, LAB_, LAB_);

    loss_kernel<<<1, 32>>>(logits, tgt, (float*)d_out, out_size);
}

// round 13
// speedup vs baseline: 1.0994x; 1.0080x over previous
#include <cuda_runtime.h>
#include <cuda_fp16.h>
#include <math.h>
#include <stdint.h>

#define B_   16
#define S_   512
#define H_   768
#define NH_  12
#define L_   6
#define FF_  3072
#define DH_  64
#define LAB_ 10
#define QKVN 2304          // 3*H

// ---------------- scratch (device globals; no allocations allowed) ----------
__device__ float  g_x   [(size_t)B_*S_*H_];
__device__ __half g_xh  [(size_t)B_*S_*H_];
__device__ __half g_qkv [(size_t)B_*S_*QKVN];
__device__ __half g_ctxh[(size_t)B_*S_*H_];
__device__ float  g_tmp [(size_t)B_*S_*H_];
__device__ __half g_ffh [(size_t)B_*S_*FF_];
__device__ float  g_hidden[(size_t)B_*H_];
__device__ float  g_logits[(size_t)B_*LAB_];
// transposed + fp16 weights [N][K]
__device__ __half g_wqkvT[(size_t)L_*QKVN*H_];
__device__ __half g_woT  [(size_t)L_*H_*H_];
__device__ __half g_wf1T [(size_t)L_*FF_*H_];
__device__ __half g_wf2T [(size_t)L_*H_*FF_];
__device__ float  g_bqkv [(size_t)L_*QKVN];

// ---------------- small helpers ----------------
__device__ __forceinline__ uint32_t smem_u32(const void* p) {
    return (uint32_t)__cvta_generic_to_shared(p);
}

__device__ __forceinline__ void cp16s(uint32_t s, const void* g) {
    asm volatile("cp.async.ca.shared.global [%0], [%1], 16;\n" :: "r"(s), "l"(g));
}

__device__ __forceinline__ void ldsm4(uint32_t* r, uint32_t a) {
    asm volatile("ldmatrix.sync.aligned.m8n8.x4.shared.b16 {%0,%1,%2,%3}, [%4];"
                 : "=r"(r[0]), "=r"(r[1]), "=r"(r[2]), "=r"(r[3]) : "r"(a));
}

__device__ __forceinline__ void ldsm4t(uint32_t* r, uint32_t a) {
    asm volatile("ldmatrix.sync.aligned.m8n8.x4.trans.shared.b16 {%0,%1,%2,%3}, [%4];"
                 : "=r"(r[0]), "=r"(r[1]), "=r"(r[2]), "=r"(r[3]) : "r"(a));
}

__device__ __forceinline__ void mma_f16(float* c, const uint32_t* a, const uint32_t* b) {
    asm volatile(
        "mma.sync.aligned.m16n8k16.row.col.f32.f16.f16.f32 "
        "{%0,%1,%2,%3}, {%4,%5,%6,%7}, {%8,%9}, {%0,%1,%2,%3};\n"
        : "+f"(c[0]), "+f"(c[1]), "+f"(c[2]), "+f"(c[3])
        : "r"(a[0]), "r"(a[1]), "r"(a[2]), "r"(a[3]), "r"(b[0]), "r"(b[1]));
}

// gelu(tanh approx) via exact identity 0.5*v*(1+tanh(u)) = v / (1 + exp(-2u)).
__device__ __forceinline__ float gelu_tanh(float v) {
    float u = 0.7978845608028654f * (v + 0.044715f * v * v * v);
    return __fdividef(v, 1.f + __expf(-2.f * u));
}

__device__ __forceinline__ float warp_sum(float v) {
    #pragma unroll
    for (int o = 16; o; o >>= 1) v += __shfl_xor_sync(0xffffffffu, v, o);
    return v;
}

__device__ __forceinline__ uint32_t pack2(float a, float b) {
    __half2 h = __floats2half2_rn(a, b);
    return *(uint32_t*)&h;
}

// ---------------- weight transpose + fp16 convert ----------------
__global__ void transpose_cvt(const float* __restrict__ in, __half* __restrict__ out,
                              int R, int C, long ozs)
{
    in  += (size_t)blockIdx.z * R * C;
    out += (size_t)blockIdx.z * ozs;
    __shared__ float t[32][33];
    int c0 = blockIdx.x * 32, r0 = blockIdx.y * 32;
    int tx = threadIdx.x, ty = threadIdx.y;
    #pragma unroll
    for (int i = 0; i < 32; i += 8)
        t[ty + i][tx] = in[(size_t)(r0 + ty + i) * C + c0 + tx];
    __syncthreads();
    #pragma unroll
    for (int i = 0; i < 32; i += 8)
        out[(size_t)(c0 + ty + i) * R + r0 + tx] = __float2half_rn(t[tx][ty + i]);
}

__global__ void concat_bias(const float* __restrict__ bq, const float* __restrict__ bk,
                            const float* __restrict__ bv, float* __restrict__ out)
{
    int i = blockIdx.x * 256 + threadIdx.x;
    if (i >= L_ * QKVN) return;
    int l = i / QKVN, r = i - l * QKVN;
    float val;
    if (r < H_)            val = bq[l * H_ + r];
    else if (r < 2 * H_)   val = bk[l * H_ + r - H_];
    else                   val = bv[l * H_ + r - 2 * H_];
    out[i] = val;
}

// ---------------- embedding + LN + selection (warp per token) ----------------
__global__ void embed_kernel(const int* __restrict__ src, const int* __restrict__ seg,
                             const int* __restrict__ tib,
                             const float* __restrict__ we, const float* __restrict__ pe,
                             const float* __restrict__ se,
                             const float* __restrict__ g, const float* __restrict__ bta,
                             const float* __restrict__ sel, float* __restrict__ x,
                             __half* __restrict__ xh)
{
    int t = blockIdx.x * 8 + (threadIdx.x >> 5);
    int lane = threadIdx.x & 31;
    int s = t % S_;
    int w = src[t], sg = seg[t];
    const float4* wr = (const float4*)(we + (size_t)w * H_);
    const float4* pr = (const float4*)(pe + (size_t)s * H_);
    const float4* sr = (const float4*)(se + (size_t)sg * H_);
    float4 v[6];
    float lsum = 0.f, lsq = 0.f;
    #pragma unroll
    for (int i = 0; i < 6; i++) {
        int idx = lane + 32 * i;
        float4 a = wr[idx], bv4 = pr[idx], c = sr[idx];
        v[i].x = a.x + bv4.x + c.x; v[i].y = a.y + bv4.y + c.y;
        v[i].z = a.z + bv4.z + c.z; v[i].w = a.w + bv4.w + c.w;
        lsum += v[i].x + v[i].y + v[i].z + v[i].w;
        lsq  += v[i].x*v[i].x + v[i].y*v[i].y + v[i].z*v[i].z + v[i].w*v[i].w;
    }
    float tot = warp_sum(lsum), totsq = warp_sum(lsq);
    float mean = tot / H_;
    float var  = totsq / H_ - mean * mean;
    float inv  = rsqrtf(var + 1e-5f);
    float f = sel[tib[t]];
    float4* xo = (float4*)(x + (size_t)t * H_);
    uint2*  xho = (uint2*)(xh + (size_t)t * H_);
    const float4* g4 = (const float4*)g;
    const float4* b4 = (const float4*)bta;
    #pragma unroll
    for (int i = 0; i < 6; i++) {
        int idx = lane + 32 * i;
        float4 gg = g4[idx], bb = b4[idx], o;
        o.x = ((v[i].x - mean) * inv * gg.x + bb.x) * f;
        o.y = ((v[i].y - mean) * inv * gg.y + bb.y) * f;
        o.z = ((v[i].z - mean) * inv * gg.z + bb.z) * f;
        o.w = ((v[i].w - mean) * inv * gg.w + bb.w) * f;
        xo[idx] = o;
        uint2 u; u.x = pack2(o.x, o.y); u.y = pack2(o.z, o.w);
        xho[idx] = u;
    }
}

// ---------------- LN over tmp (residual already fused in GEMM) --------------
__global__ void ln_kernel(const float* __restrict__ t,
                          const float* __restrict__ g, const float* __restrict__ bta,
                          float* __restrict__ x, __half* __restrict__ xh)
{
    int row = blockIdx.x * 8 + (threadIdx.x >> 5);
    int lane = threadIdx.x & 31;
    const float4* tr = (const float4*)(t + (size_t)row * H_);
    float4 v[6];
    float lsum = 0.f, lsq = 0.f;
    #pragma unroll
    for (int i = 0; i < 6; i++) {
        v[i] = tr[lane + 32 * i];
        lsum += v[i].x + v[i].y + v[i].z + v[i].w;
        lsq  += v[i].x*v[i].x + v[i].y*v[i].y + v[i].z*v[i].z + v[i].w*v[i].w;
    }
    float tot = warp_sum(lsum), totsq = warp_sum(lsq);
    float mean = tot / H_;
    float var  = totsq / H_ - mean * mean;
    float inv  = rsqrtf(var + 1e-5f);
    float4* xo = (float4*)(x + (size_t)row * H_);
    uint2*  xho = (uint2*)(xh + (size_t)row * H_);
    const float4* g4 = (const float4*)g;
    const float4* b4 = (const float4*)bta;
    #pragma unroll
    for (int i = 0; i < 6; i++) {
        int idx = lane + 32 * i;
        float4 gg = g4[idx], bb = b4[idx], o;
        o.x = (v[i].x - mean) * inv * gg.x + bb.x;
        o.y = (v[i].y - mean) * inv * gg.y + bb.y;
        o.z = (v[i].z - mean) * inv * gg.z + bb.z;
        o.w = (v[i].w - mean) * inv * gg.w + bb.w;
        xo[idx] = o;
        uint2 u; u.x = pack2(o.x, o.y); u.y = pack2(o.z, o.w);
        xho[idx] = u;
    }
}

// =====================================================================
// FP16 tensor-core GEMM: BM=128, BN=128, BK=64, 256 threads, warp tile
// 32x64, m16n8k16, 3-stage cp.async, XOR-swizzled 128B rows, one
// __syncthreads per k-tile. __launch_bounds__(256,2) forces <=128 regs
// so 2 CTAs co-reside per SM (cross-CTA latency cover).
// ACT: 0 none, 1 gelu. OUTH: 1 half out, 0 float out. RES: add Res.
// =====================================================================
#define HG_SMEM 98304   // 3 stages * (16KB A + 16KB B)

template<int ACT, int OUTH, int RES>
__global__ void __launch_bounds__(256, 2)
hgemm(const __half* __restrict__ A, const __half* __restrict__ Bw,
      const float* __restrict__ bias, void* __restrict__ Cout,
      const float* __restrict__ Res,
      int K, int lda, int ldb, int ldc)
{
    extern __shared__ char smem[];
    const uint32_t sb = smem_u32(smem);

    const int m0  = blockIdx.y * 128;
    const int n0  = blockIdx.x * 128;
    const int tid = threadIdx.x;
    const int lane = tid & 31, wid = tid >> 5;
    const int wm = wid & 3, wn = wid >> 2;
    const int g = lane >> 2, t = lane & 3;

    const int nt = K >> 6;     // BK = 64 halves = 128B rows

    auto load_st = [&](int kt) {
        int st = kt % 3;
        int k0 = kt << 6;
        uint32_t ab = sb + st * 32768;
        uint32_t bb = ab + 16384;
        #pragma unroll
        for (int i = 0; i < 4; i++) {
            int c = i * 256 + tid;              // 1024 chunks per operand
            int row = c >> 3, ch = c & 7;
            uint32_t d = ((uint32_t)row << 7) + (uint32_t)((ch ^ (row & 7)) << 4);
            cp16s(ab + d, A  + (size_t)(m0 + row) * lda + k0 + ch * 8);
            cp16s(bb + d, Bw + (size_t)(n0 + row) * ldb + k0 + ch * 8);
        }
        asm volatile("cp.async.commit_group;" ::: "memory");
    };

    float acc[2][8][4];
    #pragma unroll
    for (int i = 0; i < 2; i++)
        #pragma unroll
        for (int j = 0; j < 8; j++)
            #pragma unroll
            for (int r = 0; r < 4; r++) acc[i][j][r] = 0.f;

    load_st(0);
    if (nt > 1) load_st(1);

    const int arow_b = wm * 32 + (lane & 15);                       // + mt*16
    const int achk_b = (lane >> 4);                                 // + ks*2
    const int brow_b = wn * 64 + ((lane >> 4) << 3) + (lane & 7);   // + p*16
    const int bchk_b = ((lane >> 3) & 1);                           // + ks*2

    for (int kt = 0; kt < nt; kt++) {
        int st = kt % 3;
        if (kt + 1 < nt)
            asm volatile("cp.async.wait_group 1;" ::: "memory");
        else
            asm volatile("cp.async.wait_group 0;" ::: "memory");
        __syncthreads();
        if (kt + 2 < nt) load_st(kt + 2);

        uint32_t ab = sb + st * 32768;
        uint32_t bb = ab + 16384;

        #pragma unroll
        for (int ks = 0; ks < 4; ks++) {
            uint32_t afr[2][4];
            #pragma unroll
            for (int mt = 0; mt < 2; mt++) {
                int row = arow_b + mt * 16;
                int ch  = achk_b + ks * 2;
                ldsm4(afr[mt], ab + ((uint32_t)row << 7)
                                  + (uint32_t)((ch ^ (row & 7)) << 4));
            }
            uint32_t bfr[8][2];
            #pragma unroll
            for (int p = 0; p < 4; p++) {
                int row = brow_b + p * 16;
                int ch  = bchk_b + ks * 2;
                uint32_t rr[4];
                ldsm4(rr, bb + ((uint32_t)row << 7)
                             + (uint32_t)((ch ^ (row & 7)) << 4));
                bfr[2 * p][0]     = rr[0]; bfr[2 * p][1]     = rr[1];
                bfr[2 * p + 1][0] = rr[2]; bfr[2 * p + 1][1] = rr[3];
            }
            #pragma unroll
            for (int mt = 0; mt < 2; mt++)
                #pragma unroll
                for (int ntl = 0; ntl < 8; ntl++)
                    mma_f16(acc[mt][ntl], afr[mt], bfr[ntl]);
        }
    }

    #pragma unroll
    for (int mt = 0; mt < 2; mt++) {
        #pragma unroll
        for (int ntl = 0; ntl < 8; ntl++) {
            int row = m0 + wm * 32 + mt * 16 + g;
            int col = n0 + wn * 64 + ntl * 8 + t * 2;
            float2 bv = *(const float2*)&bias[col];
            #pragma unroll
            for (int half_ = 0; half_ < 2; half_++) {
                int r = row + half_ * 8;
                float v0 = acc[mt][ntl][half_ * 2 + 0] + bv.x;
                float v1 = acc[mt][ntl][half_ * 2 + 1] + bv.y;
                if (ACT == 1) { v0 = gelu_tanh(v0); v1 = gelu_tanh(v1); }
                if (RES) {
                    float2 rr = *(const float2*)&Res[(size_t)r * ldc + col];
                    v0 += rr.x; v1 += rr.y;
                }
                if (OUTH) {
                    __half2* C = (__half2*)((__half*)Cout + (size_t)r * ldc + col);
                    *C = __floats2half2_rn(v0, v1);
                } else {
                    float* C = (float*)Cout + (size_t)r * ldc + col;
                    *(float2*)C = make_float2(v0, v1);
                }
            }
        }
    }
}

// =====================================================================
// Fused flash-attention: P fragments formed directly in registers.
// =====================================================================
#define ATTN_SMEM  ((128*72 + 2*64*72 + 2*64*72) * 2 + 512 * 4)   // 57344

__global__ void __launch_bounds__(256)
attn_kernel(const __half* __restrict__ qkv, const int* __restrict__ seg,
            __half* __restrict__ ctx)
{
    extern __shared__ __half hsm[];
    __half* sP    = hsm;                       // 128*72 (Q staging)
    __half* sK    = sP + 128 * 72;             // 2 * 64*72
    __half* sV    = sK + 2 * 64 * 72;          // 2 * 64*72
    float*  smask = (float*)(sV + 2 * 64 * 72);

    const int bh = blockIdx.y;
    const int b = bh / NH_, h = bh - b * NH_;
    const int q0 = blockIdx.x * 128;

    const __half* qp = qkv + (size_t)b * S_ * QKVN + h * DH_;
    const __half* kp = qp + H_;
    __half* cp = ctx + ((size_t)b * S_ + q0) * H_ + h * DH_;

    const int tid = threadIdx.x, lane = tid & 31, wid = tid >> 5;
    const int g = lane >> 2, t = lane & 3;
    const uint32_t sPb = smem_u32(sP);
    const uint32_t sKb0 = smem_u32(sK);
    const uint32_t sVb0 = smem_u32(sV);

    for (int i = tid; i < S_; i += 256)
        smask[i] = (seg[b * S_ + i] > 0) ? 0.f : -1e9f;

    #pragma unroll
    for (int i = 0; i < 4; i++) {
        int c = i * 256 + tid;
        int row = c >> 3, kc = (c & 7) << 3;
        cp16s(sPb + (uint32_t)row * 144 + ((c & 7) << 4),
              qp + (size_t)(q0 + row) * QKVN + kc);
    }
    asm volatile("cp.async.commit_group;" ::: "memory");
    asm volatile("cp.async.wait_group 0;" ::: "memory");
    __syncthreads();

    const uint32_t a_base = (uint32_t)(wid * 16 + (lane & 15)) * 144 + ((lane >> 4) << 4);
    uint32_t qf[4][4];
    #pragma unroll
    for (int s = 0; s < 4; s++)
        ldsm4(qf[s], sPb + a_base + s * 32);
    __syncthreads();

    auto load_kv = [&](int kt, int buf) {
        int kbase = kt * 64;
        #pragma unroll
        for (int i = 0; i < 2; i++) {
            int c = i * 256 + tid;
            int row = c >> 3, kc = (c & 7) << 3;
            const __half* kg = kp + (size_t)(kbase + row) * QKVN + kc;
            uint32_t d = (uint32_t)row * 144 + ((c & 7) << 4);
            cp16s(sKb0 + buf * 9216 + d, kg);
            cp16s(sVb0 + buf * 9216 + d, kg + H_);
        }
        asm volatile("cp.async.commit_group;" ::: "memory");
    };
    load_kv(0, 0);

    const uint32_t bK_base = (uint32_t)(((lane >> 4) << 3) + (lane & 7)) * 144
                           + (((lane >> 3) & 1) << 4);
    const uint32_t bV_base = (uint32_t)(lane & 15) * 144 + (((lane >> 4) & 1) << 4);

    float m_run[2] = {-1e30f, -1e30f};
    float l_run[2] = {0.f, 0.f};
    float o[8][4];
    #pragma unroll
    for (int ntl = 0; ntl < 8; ntl++)
        #pragma unroll
        for (int r = 0; r < 4; r++) o[ntl][r] = 0.f;

    for (int kt = 0; kt < S_ / 64; kt++) {
        int buf = kt & 1;
        asm volatile("cp.async.wait_group 0;" ::: "memory");
        __syncthreads();
        if (kt + 1 < S_ / 64) load_kv(kt + 1, buf ^ 1);

        uint32_t sKb = sKb0 + buf * 9216;
        uint32_t sVb = sVb0 + buf * 9216;

        // S = Q @ K^T
        float sacc[8][4];
        #pragma unroll
        for (int ntl = 0; ntl < 8; ntl++)
            #pragma unroll
            for (int r = 0; r < 4; r++) sacc[ntl][r] = 0.f;
        #pragma unroll
        for (int s = 0; s < 4; s++) {
            uint32_t bfr[8][2];
            #pragma unroll
            for (int p = 0; p < 4; p++) {
                uint32_t rr[4];
                ldsm4(rr, sKb + bK_base + p * (16 * 144) + s * 32);
                bfr[2 * p][0]     = rr[0]; bfr[2 * p][1]     = rr[1];
                bfr[2 * p + 1][0] = rr[2]; bfr[2 * p + 1][1] = rr[3];
            }
            #pragma unroll
            for (int ntl = 0; ntl < 8; ntl++)
                mma_f16(sacc[ntl], qf[s], bfr[ntl]);
        }

        // scale + mask + online softmax
        float tmax0 = -1e30f, tmax1 = -1e30f;
        #pragma unroll
        for (int ntl = 0; ntl < 8; ntl++) {
            int col = kt * 64 + ntl * 8 + t * 2;
            float mb0 = smask[col], mb1 = smask[col + 1];
            sacc[ntl][0] = fmaf(sacc[ntl][0], 0.125f, mb0);
            sacc[ntl][1] = fmaf(sacc[ntl][1], 0.125f, mb1);
            sacc[ntl][2] = fmaf(sacc[ntl][2], 0.125f, mb0);
            sacc[ntl][3] = fmaf(sacc[ntl][3], 0.125f, mb1);
            tmax0 = fmaxf(tmax0, fmaxf(sacc[ntl][0], sacc[ntl][1]));
            tmax1 = fmaxf(tmax1, fmaxf(sacc[ntl][2], sacc[ntl][3]));
        }
        tmax0 = fmaxf(tmax0, __shfl_xor_sync(0xffffffffu, tmax0, 1));
        tmax0 = fmaxf(tmax0, __shfl_xor_sync(0xffffffffu, tmax0, 2));
        tmax1 = fmaxf(tmax1, __shfl_xor_sync(0xffffffffu, tmax1, 1));
        tmax1 = fmaxf(tmax1, __shfl_xor_sync(0xffffffffu, tmax1, 2));
        float mnew0 = fmaxf(m_run[0], tmax0);
        float mnew1 = fmaxf(m_run[1], tmax1);
        float al0 = __expf(m_run[0] - mnew0);
        float al1 = __expf(m_run[1] - mnew1);
        float ts0 = 0.f, ts1 = 0.f;
        #pragma unroll
        for (int ntl = 0; ntl < 8; ntl++) {
            sacc[ntl][0] = __expf(sacc[ntl][0] - mnew0);
            sacc[ntl][1] = __expf(sacc[ntl][1] - mnew0);
            sacc[ntl][2] = __expf(sacc[ntl][2] - mnew1);
            sacc[ntl][3] = __expf(sacc[ntl][3] - mnew1);
            ts0 += sacc[ntl][0] + sacc[ntl][1];
            ts1 += sacc[ntl][2] + sacc[ntl][3];
        }
        ts0 += __shfl_xor_sync(0xffffffffu, ts0, 1);
        ts0 += __shfl_xor_sync(0xffffffffu, ts0, 2);
        ts1 += __shfl_xor_sync(0xffffffffu, ts1, 1);
        ts1 += __shfl_xor_sync(0xffffffffu, ts1, 2);
        l_run[0] = l_run[0] * al0 + ts0;
        l_run[1] = l_run[1] * al1 + ts1;
        m_run[0] = mnew0; m_run[1] = mnew1;
        #pragma unroll
        for (int ntl = 0; ntl < 8; ntl++) {
            o[ntl][0] *= al0; o[ntl][1] *= al0;
            o[ntl][2] *= al1; o[ntl][3] *= al1;
        }

        // P @ V : P fragments built directly from sacc registers.
        #pragma unroll
        for (int s = 0; s < 4; s++) {
            uint32_t pf[4];
            pf[0] = pack2(sacc[2*s][0],   sacc[2*s][1]);
            pf[1] = pack2(sacc[2*s][2],   sacc[2*s][3]);
            pf[2] = pack2(sacc[2*s+1][0], sacc[2*s+1][1]);
            pf[3] = pack2(sacc[2*s+1][2], sacc[2*s+1][3]);
            uint32_t bfr[8][2];
            #pragma unroll
            for (int p = 0; p < 4; p++) {
                uint32_t rr[4];
                ldsm4t(rr, sVb + bV_base + s * (16 * 144) + p * 32);
                bfr[2 * p][0]     = rr[0]; bfr[2 * p][1]     = rr[1];
                bfr[2 * p + 1][0] = rr[2]; bfr[2 * p + 1][1] = rr[3];
            }
            #pragma unroll
            for (int ntl = 0; ntl < 8; ntl++)
                mma_f16(o[ntl], pf, bfr[ntl]);
        }
    }

    float rl0 = 1.f / l_run[0], rl1 = 1.f / l_run[1];
    int r0 = wid * 16 + g;
    #pragma unroll
    for (int ntl = 0; ntl < 8; ntl++) {
        int col = ntl * 8 + t * 2;
        *(__half2*)&cp[(size_t)r0 * H_ + col] =
            __floats2half2_rn(o[ntl][0] * rl0, o[ntl][1] * rl0);
        *(__half2*)&cp[(size_t)(r0 + 8) * H_ + col] =
            __floats2half2_rn(o[ntl][2] * rl1, o[ntl][3] * rl1);
    }
}

// ---------------- small SIMT GEMM (pooler + classifier only) ----------------
template<int ACT> // 0 none, 2 tanh
__global__ void gemm_kernel(const float* __restrict__ A, const float* __restrict__ Bm,
                            const float* __restrict__ bias, float* __restrict__ C,
                            int M, int N, int K, int lda, int ldb, int ldc)
{
    __shared__ float As[16][65];
    __shared__ float Bs[16][65];

    int m0 = blockIdx.y * 64;
    int n0 = blockIdx.x * 64;
    int tid = threadIdx.x;
    int tx = tid & 15, ty = tid >> 4;

    float acc[4][4] = {};

    for (int k0 = 0; k0 < K; k0 += 16) {
        #pragma unroll
        for (int i = tid; i < 64 * 16; i += 256) {
            int m = i >> 4, k = i & 15;
            int gm = m0 + m, gk = k0 + k;
            As[k][m] = (gm < M && gk < K) ? A[(long)gm * lda + gk] : 0.f;
        }
        #pragma unroll
        for (int i = tid; i < 16 * 64; i += 256) {
            int k = i >> 6, n = i & 63;
            int gk = k0 + k, gn = n0 + n;
            Bs[k][n] = (gk < K && gn < N) ? Bm[(long)gk * ldb + gn] : 0.f;
        }
        __syncthreads();
        #pragma unroll
        for (int k = 0; k < 16; k++) {
            float a[4], bb[4];
            #pragma unroll
            for (int i = 0; i < 4; i++) a[i] = As[k][ty * 4 + i];
            #pragma unroll
            for (int j = 0; j < 4; j++) bb[j] = Bs[k][tx * 4 + j];
            #pragma unroll
            for (int i = 0; i < 4; i++)
                #pragma unroll
                for (int j = 0; j < 4; j++)
                    acc[i][j] = fmaf(a[i], bb[j], acc[i][j]);
        }
        __syncthreads();
    }

    #pragma unroll
    for (int i = 0; i < 4; i++) {
        int gm = m0 + ty * 4 + i;
        if (gm >= M) continue;
        #pragma unroll
        for (int j = 0; j < 4; j++) {
            int gn = n0 + tx * 4 + j;
            if (gn >= N) continue;
            float v = acc[i][j];
            if (bias) v += bias[gn];
            if (ACT == 2) v = tanhf(v);
            C[(long)gm * ldc + gn] = v;
        }
    }
}

// ---------------- log-softmax + NLL loss + output write ----------------
__global__ void loss_kernel(const float* __restrict__ logits, const int* __restrict__ tgt,
                            float* __restrict__ out, int out_size)
{
    int lane = threadIdx.x;
    float lp = 0.f;
    if (lane < B_) {
        const float* row = logits + lane * LAB_;
        float mx = row[0];
        #pragma unroll
        for (int j = 1; j < LAB_; j++) mx = fmaxf(mx, row[j]);
        float s = 0.f;
        #pragma unroll
        for (int j = 0; j < LAB_; j++) s += expf(row[j] - mx);
        lp = row[tgt[lane]] - mx - logf(s);
    }
    #pragma unroll
    for (int o = 16; o; o >>= 1) lp += __shfl_down_sync(0xffffffffu, lp, o);
    int ofs = (out_size > B_ * LAB_) ? 1 : 0;
    if (lane == 0 && ofs) out[0] = -lp / (float)B_;
    for (int i = lane; i < B_ * LAB_; i += 32) out[ofs + i] = logits[i];
}

// ---------------- host launch ----------------
extern "C" void kernel_launch(void* const* d_in, const int* in_sizes, int n_in,
                              void* d_out, int out_size)
{
    const int*   src  = (const int*)d_in[0];
    const int*   seg  = (const int*)d_in[1];
    const int*   tgt  = (const int*)d_in[2];
    const int*   tib  = (const int*)d_in[3];
    const float* we   = (const float*)d_in[4];
    const float* pe   = (const float*)d_in[5];
    const float* se   = (const float*)d_in[6];
    const float* elng = (const float*)d_in[7];
    const float* elnb = (const float*)d_in[8];
    const float* Wq   = (const float*)d_in[9];
    const float* bq   = (const float*)d_in[10];
    const float* Wk   = (const float*)d_in[11];
    const float* bk   = (const float*)d_in[12];
    const float* Wv   = (const float*)d_in[13];
    const float* bv   = (const float*)d_in[14];
    const float* Wo   = (const float*)d_in[15];
    const float* bo   = (const float*)d_in[16];
    const float* ln1g = (const float*)d_in[17];
    const float* ln1b = (const float*)d_in[18];
    const float* Wf1  = (const float*)d_in[19];
    const float* bf1  = (const float*)d_in[20];
    const float* Wf2  = (const float*)d_in[21];
    const float* bf2  = (const float*)d_in[22];
    const float* ln2g = (const float*)d_in[23];
    const float* ln2b = (const float*)d_in[24];
    const float* Wp1  = (const float*)d_in[25];
    const float* bp1  = (const float*)d_in[26];
    const float* Wp2  = (const float*)d_in[27];
    const float* bp2  = (const float*)d_in[28];
    const float* sel  = (const float*)d_in[29];
    (void)in_sizes; (void)n_in;

    float *x, *tmp, *hidden, *logits, *bqkv;
    __half *xh, *qkv, *ctxh, *ffh, *wqkvT, *woT, *wf1T, *wf2T;
    cudaGetSymbolAddress((void**)&x,     g_x);
    cudaGetSymbolAddress((void**)&xh,    g_xh);
    cudaGetSymbolAddress((void**)&qkv,   g_qkv);
    cudaGetSymbolAddress((void**)&ctxh,  g_ctxh);
    cudaGetSymbolAddress((void**)&tmp,   g_tmp);
    cudaGetSymbolAddress((void**)&ffh,   g_ffh);
    cudaGetSymbolAddress((void**)&hidden,g_hidden);
    cudaGetSymbolAddress((void**)&logits,g_logits);
    cudaGetSymbolAddress((void**)&wqkvT, g_wqkvT);
    cudaGetSymbolAddress((void**)&woT,   g_woT);
    cudaGetSymbolAddress((void**)&wf1T,  g_wf1T);
    cudaGetSymbolAddress((void**)&wf2T,  g_wf2T);
    cudaGetSymbolAddress((void**)&bqkv,  g_bqkv);

    cudaFuncSetAttribute((const void*)hgemm<0,1,0>, cudaFuncAttributeMaxDynamicSharedMemorySize, HG_SMEM);
    cudaFuncSetAttribute((const void*)hgemm<0,0,1>, cudaFuncAttributeMaxDynamicSharedMemorySize, HG_SMEM);
    cudaFuncSetAttribute((const void*)hgemm<1,1,0>, cudaFuncAttributeMaxDynamicSharedMemorySize, HG_SMEM);
    cudaFuncSetAttribute((const void*)attn_kernel,  cudaFuncAttributeMaxDynamicSharedMemorySize, ATTN_SMEM);

    const int Mtok = B_ * S_;                    // 8192

    // weight prep
    {
        dim3 tb(32, 8);
        dim3 gHH(H_ / 32, H_ / 32, L_);
        transpose_cvt<<<gHH, tb>>>(Wq, wqkvT,                   H_, H_, (long)QKVN * H_);
        transpose_cvt<<<gHH, tb>>>(Wk, wqkvT + (size_t)H_*H_,   H_, H_, (long)QKVN * H_);
        transpose_cvt<<<gHH, tb>>>(Wv, wqkvT + (size_t)2*H_*H_, H_, H_, (long)QKVN * H_);
        transpose_cvt<<<gHH, tb>>>(Wo, woT, H_, H_, (long)H_ * H_);
        dim3 gF1(FF_ / 32, H_ / 32, L_);
        transpose_cvt<<<gF1, tb>>>(Wf1, wf1T, H_, FF_, (long)FF_ * H_);
        dim3 gF2(H_ / 32, FF_ / 32, L_);
        transpose_cvt<<<gF2, tb>>>(Wf2, wf2T, FF_, H_, (long)H_ * FF_);
        concat_bias<<<(L_ * QKVN + 255) / 256, 256>>>(bq, bk, bv, bqkv);
    }

    embed_kernel<<<Mtok / 8, 256>>>(src, seg, tib, we, pe, se, elng, elnb, sel, x, xh);

    dim3 gQKV(QKVN / 128, Mtok / 128);   // (18, 64)
    dim3 gH  (H_   / 128, Mtok / 128);   // (6, 64)
    dim3 gFF (FF_  / 128, Mtok / 128);   // (24, 64)
    dim3 gAtt(S_ / 128, B_ * NH_);       // (4, 192)

    for (int l = 0; l < L_; l++) {
        const __half* wqkv = wqkvT + (size_t)l * QKVN * H_;
        const __half* wo   = woT   + (size_t)l * H_ * H_;
        const __half* wf1  = wf1T  + (size_t)l * H_ * FF_;
        const __half* wf2  = wf2T  + (size_t)l * FF_ * H_;

        hgemm<0,1,0><<<gQKV, 256, HG_SMEM>>>(xh, wqkv, bqkv + l * QKVN, qkv, nullptr,
                                             H_, H_, H_, QKVN);
        attn_kernel<<<gAtt, 256, ATTN_SMEM>>>(qkv, seg, ctxh);
        // tmp = ctx @ Wo + bo + x  (residual fused)
        hgemm<0,0,1><<<gH, 256, HG_SMEM>>>(ctxh, wo, bo + l * H_, tmp, x,
                                           H_, H_, H_, H_);
        ln_kernel<<<Mtok / 8, 256>>>(tmp, ln1g + l * H_, ln1b + l * H_, x, xh);

        hgemm<1,1,0><<<gFF, 256, HG_SMEM>>>(xh, wf1, bf1 + l * FF_, ffh, nullptr,
                                            H_, H_, H_, FF_);
        // tmp = gelu_ff @ Wf2 + bf2 + x  (residual fused)
        hgemm<0,0,1><<<gH, 256, HG_SMEM>>>(ffh, wf2, bf2 + l * H_, tmp, x,
                                           FF_, FF_, FF_, H_);
        ln_kernel<<<Mtok / 8, 256>>>(tmp, ln2g + l * H_, ln2b + l * H_, x, xh);
    }

    dim3 gPool((H_ + 63) / 64, 1);
    gemm_kernel<2><<<gPool, 256>>>(x, Wp1, bp1, hidden, B_, H_, H_,
                                   S_ * H_, H_, H_);
    dim3 gCls(1, 1);
    gemm_kernel<0><<<gCls, 256>>>(hidden, Wp2, bp2, logits, B_, LAB_, H_,
                                  H_, LAB_, LAB_);

    loss_kernel<<<1, 32>>>(logits, tgt, (float*)d_out, out_size);
}

// round 14
// speedup vs baseline: 1.1372x; 1.0343x over previous
#include <cuda_runtime.h>
#include <cuda_fp16.h>
#include <math.h>
#include <stdint.h>

#define B_   16
#define S_   512
#define H_   768
#define NH_  12
#define L_   6
#define FF_  3072
#define DH_  64
#define LAB_ 10
#define QKVN 2304          // 3*H

// ---------------- scratch (device globals; no allocations allowed) ----------
__device__ float  g_x   [(size_t)B_*S_*H_];
__device__ __half g_xh  [(size_t)B_*S_*H_];
__device__ __half g_qkv [(size_t)B_*S_*QKVN];
__device__ __half g_ctxh[(size_t)B_*S_*H_];
__device__ float  g_tmp [(size_t)B_*S_*H_];
__device__ __half g_ffh [(size_t)B_*S_*FF_];
__device__ float  g_hidden[(size_t)B_*H_];
__device__ float  g_logits[(size_t)B_*LAB_];
// transposed + fp16 weights [N][K]
__device__ __half g_wqkvT[(size_t)L_*QKVN*H_];
__device__ __half g_woT  [(size_t)L_*H_*H_];
__device__ __half g_wf1T [(size_t)L_*FF_*H_];
__device__ __half g_wf2T [(size_t)L_*H_*FF_];
__device__ float  g_bqkv [(size_t)L_*QKVN];

// ---------------- small helpers ----------------
__device__ __forceinline__ uint32_t smem_u32(const void* p) {
    return (uint32_t)__cvta_generic_to_shared(p);
}

__device__ __forceinline__ void cp16s(uint32_t s, const void* g) {
    asm volatile("cp.async.ca.shared.global [%0], [%1], 16;\n" :: "r"(s), "l"(g));
}

__device__ __forceinline__ void ldsm4(uint32_t* r, uint32_t a) {
    asm volatile("ldmatrix.sync.aligned.m8n8.x4.shared.b16 {%0,%1,%2,%3}, [%4];"
                 : "=r"(r[0]), "=r"(r[1]), "=r"(r[2]), "=r"(r[3]) : "r"(a));
}

__device__ __forceinline__ void ldsm4t(uint32_t* r, uint32_t a) {
    asm volatile("ldmatrix.sync.aligned.m8n8.x4.trans.shared.b16 {%0,%1,%2,%3}, [%4];"
                 : "=r"(r[0]), "=r"(r[1]), "=r"(r[2]), "=r"(r[3]) : "r"(a));
}

__device__ __forceinline__ void mma_f16(float* c, const uint32_t* a, const uint32_t* b) {
    asm volatile(
        "mma.sync.aligned.m16n8k16.row.col.f32.f16.f16.f32 "
        "{%0,%1,%2,%3}, {%4,%5,%6,%7}, {%8,%9}, {%0,%1,%2,%3};\n"
        : "+f"(c[0]), "+f"(c[1]), "+f"(c[2]), "+f"(c[3])
        : "r"(a[0]), "r"(a[1]), "r"(a[2]), "r"(a[3]), "r"(b[0]), "r"(b[1]));
}

// gelu(tanh approx) via exact identity 0.5*v*(1+tanh(u)) = v / (1 + exp(-2u)).
__device__ __forceinline__ float gelu_tanh(float v) {
    float u = 0.7978845608028654f * (v + 0.044715f * v * v * v);
    return __fdividef(v, 1.f + __expf(-2.f * u));
}

__device__ __forceinline__ float warp_sum(float v) {
    #pragma unroll
    for (int o = 16; o; o >>= 1) v += __shfl_xor_sync(0xffffffffu, v, o);
    return v;
}

__device__ __forceinline__ uint32_t pack2(float a, float b) {
    __half2 h = __floats2half2_rn(a, b);
    return *(uint32_t*)&h;
}

// ---------------- weight transpose + fp16 convert ----------------
__global__ void transpose_cvt(const float* __restrict__ in, __half* __restrict__ out,
                              int R, int C, long ozs)
{
    in  += (size_t)blockIdx.z * R * C;
    out += (size_t)blockIdx.z * ozs;
    __shared__ float t[32][33];
    int c0 = blockIdx.x * 32, r0 = blockIdx.y * 32;
    int tx = threadIdx.x, ty = threadIdx.y;
    #pragma unroll
    for (int i = 0; i < 32; i += 8)
        t[ty + i][tx] = in[(size_t)(r0 + ty + i) * C + c0 + tx];
    __syncthreads();
    #pragma unroll
    for (int i = 0; i < 32; i += 8)
        out[(size_t)(c0 + ty + i) * R + r0 + tx] = __float2half_rn(t[tx][ty + i]);
}

__global__ void concat_bias(const float* __restrict__ bq, const float* __restrict__ bk,
                            const float* __restrict__ bv, float* __restrict__ out)
{
    int i = blockIdx.x * 256 + threadIdx.x;
    if (i >= L_ * QKVN) return;
    int l = i / QKVN, r = i - l * QKVN;
    float val;
    if (r < H_)            val = bq[l * H_ + r];
    else if (r < 2 * H_)   val = bk[l * H_ + r - H_];
    else                   val = bv[l * H_ + r - 2 * H_];
    out[i] = val;
}

// ---------------- embedding + LN + selection (warp per token) ----------------
__global__ void embed_kernel(const int* __restrict__ src, const int* __restrict__ seg,
                             const int* __restrict__ tib,
                             const float* __restrict__ we, const float* __restrict__ pe,
                             const float* __restrict__ se,
                             const float* __restrict__ g, const float* __restrict__ bta,
                             const float* __restrict__ sel, float* __restrict__ x,
                             __half* __restrict__ xh)
{
    int t = blockIdx.x * 8 + (threadIdx.x >> 5);
    int lane = threadIdx.x & 31;
    int s = t % S_;
    int w = src[t], sg = seg[t];
    const float4* wr = (const float4*)(we + (size_t)w * H_);
    const float4* pr = (const float4*)(pe + (size_t)s * H_);
    const float4* sr = (const float4*)(se + (size_t)sg * H_);
    float4 v[6];
    float lsum = 0.f, lsq = 0.f;
    #pragma unroll
    for (int i = 0; i < 6; i++) {
        int idx = lane + 32 * i;
        float4 a = wr[idx], bv4 = pr[idx], c = sr[idx];
        v[i].x = a.x + bv4.x + c.x; v[i].y = a.y + bv4.y + c.y;
        v[i].z = a.z + bv4.z + c.z; v[i].w = a.w + bv4.w + c.w;
        lsum += v[i].x + v[i].y + v[i].z + v[i].w;
        lsq  += v[i].x*v[i].x + v[i].y*v[i].y + v[i].z*v[i].z + v[i].w*v[i].w;
    }
    float tot = warp_sum(lsum), totsq = warp_sum(lsq);
    float mean = tot / H_;
    float var  = totsq / H_ - mean * mean;
    float inv  = rsqrtf(var + 1e-5f);
    float f = sel[tib[t]];
    float4* xo = (float4*)(x + (size_t)t * H_);
    uint2*  xho = (uint2*)(xh + (size_t)t * H_);
    const float4* g4 = (const float4*)g;
    const float4* b4 = (const float4*)bta;
    #pragma unroll
    for (int i = 0; i < 6; i++) {
        int idx = lane + 32 * i;
        float4 gg = g4[idx], bb = b4[idx], o;
        o.x = ((v[i].x - mean) * inv * gg.x + bb.x) * f;
        o.y = ((v[i].y - mean) * inv * gg.y + bb.y) * f;
        o.z = ((v[i].z - mean) * inv * gg.z + bb.z) * f;
        o.w = ((v[i].w - mean) * inv * gg.w + bb.w) * f;
        xo[idx] = o;
        uint2 u; u.x = pack2(o.x, o.y); u.y = pack2(o.z, o.w);
        xho[idx] = u;
    }
}

// ---------------- LN over tmp (residual already fused in GEMM) --------------
__global__ void ln_kernel(const float* __restrict__ t,
                          const float* __restrict__ g, const float* __restrict__ bta,
                          float* __restrict__ x, __half* __restrict__ xh)
{
    int row = blockIdx.x * 8 + (threadIdx.x >> 5);
    int lane = threadIdx.x & 31;
    const float4* tr = (const float4*)(t + (size_t)row * H_);
    float4 v[6];
    float lsum = 0.f, lsq = 0.f;
    #pragma unroll
    for (int i = 0; i < 6; i++) {
        v[i] = tr[lane + 32 * i];
        lsum += v[i].x + v[i].y + v[i].z + v[i].w;
        lsq  += v[i].x*v[i].x + v[i].y*v[i].y + v[i].z*v[i].z + v[i].w*v[i].w;
    }
    float tot = warp_sum(lsum), totsq = warp_sum(lsq);
    float mean = tot / H_;
    float var  = totsq / H_ - mean * mean;
    float inv  = rsqrtf(var + 1e-5f);
    float4* xo = (float4*)(x + (size_t)row * H_);
    uint2*  xho = (uint2*)(xh + (size_t)row * H_);
    const float4* g4 = (const float4*)g;
    const float4* b4 = (const float4*)bta;
    #pragma unroll
    for (int i = 0; i < 6; i++) {
        int idx = lane + 32 * i;
        float4 gg = g4[idx], bb = b4[idx], o;
        o.x = (v[i].x - mean) * inv * gg.x + bb.x;
        o.y = (v[i].y - mean) * inv * gg.y + bb.y;
        o.z = (v[i].z - mean) * inv * gg.z + bb.z;
        o.w = (v[i].w - mean) * inv * gg.w + bb.w;
        xo[idx] = o;
        uint2 u; u.x = pack2(o.x, o.y); u.y = pack2(o.z, o.w);
        xho[idx] = u;
    }
}

// =====================================================================
// FP16 tensor-core GEMM: BM=128, BN=128, BK=64, 256 threads, warp tile
// 32x64, m16n8k16, 3-stage cp.async, XOR-swizzled 128B rows, one
// __syncthreads per k-tile, 2 CTAs/SM. Swizzled ldsm offsets and copy
// addresses PRECOMPUTED per thread (inner loop = ADD + LDSM + MMA only).
// ACT: 0 none, 1 gelu. OUTH: 1 half out, 0 float out. RES: add Res.
// =====================================================================
#define HG_SMEM 98304   // 3 stages * (16KB A + 16KB B)

template<int ACT, int OUTH, int RES>
__global__ void __launch_bounds__(256, 2)
hgemm(const __half* __restrict__ A, const __half* __restrict__ Bw,
      const float* __restrict__ bias, void* __restrict__ Cout,
      const float* __restrict__ Res,
      int K, int lda, int ldb, int ldc)
{
    extern __shared__ char smem[];
    const uint32_t sb = smem_u32(smem);

    const int m0  = blockIdx.y * 128;
    const int n0  = blockIdx.x * 128;
    const int tid = threadIdx.x;
    const int lane = tid & 31, wid = tid >> 5;
    const int wm = wid & 3, wn = wid >> 2;
    const int g = lane >> 2, t = lane & 3;

    const int nt = K >> 6;     // BK = 64 halves = 128B rows

    // ---- precomputed copy addressing (per thread; same every k-tile) ----
    uint32_t cp_d[4];
    const __half* aP[4];
    const __half* bP[4];
    #pragma unroll
    for (int i = 0; i < 4; i++) {
        int c = i * 256 + tid;
        int row = c >> 3, ch = c & 7;
        cp_d[i] = ((uint32_t)row << 7) + (uint32_t)((ch ^ (row & 7)) << 4);
        aP[i] = A  + (size_t)(m0 + row) * lda + ch * 8;
        bP[i] = Bw + (size_t)(n0 + row) * ldb + ch * 8;
    }

    auto load_st = [&](int kt) {
        int st = kt % 3;
        int k0 = kt << 6;
        uint32_t ab = sb + st * 32768;
        uint32_t bb = ab + 16384;
        #pragma unroll
        for (int i = 0; i < 4; i++) {
            cp16s(ab + cp_d[i], aP[i] + k0);
            cp16s(bb + cp_d[i], bP[i] + k0);
        }
        asm volatile("cp.async.commit_group;" ::: "memory");
    };

    // ---- precomputed ldsm swizzled offsets (row&7 invariant under +16) ----
    const int arow_b = wm * 32 + (lane & 15);
    const int achk_b = (lane >> 4);
    const int brow_b = wn * 64 + ((lane >> 4) << 3) + (lane & 7);
    const int bchk_b = ((lane >> 3) & 1);
    uint32_t a_sw[4], b_sw[4];
    #pragma unroll
    for (int ks = 0; ks < 4; ks++) {
        a_sw[ks] = ((uint32_t)arow_b << 7)
                 + (uint32_t)(((achk_b + ks * 2) ^ (arow_b & 7)) << 4);
        b_sw[ks] = ((uint32_t)brow_b << 7)
                 + (uint32_t)(((bchk_b + ks * 2) ^ (brow_b & 7)) << 4);
    }

    float acc[2][8][4];
    #pragma unroll
    for (int i = 0; i < 2; i++)
        #pragma unroll
        for (int j = 0; j < 8; j++)
            #pragma unroll
            for (int r = 0; r < 4; r++) acc[i][j][r] = 0.f;

    load_st(0);
    if (nt > 1) load_st(1);

    for (int kt = 0; kt < nt; kt++) {
        int st = kt % 3;
        if (kt + 1 < nt)
            asm volatile("cp.async.wait_group 1;" ::: "memory");
        else
            asm volatile("cp.async.wait_group 0;" ::: "memory");
        __syncthreads();
        if (kt + 2 < nt) load_st(kt + 2);

        uint32_t ab = sb + st * 32768;
        uint32_t bb = ab + 16384;

        #pragma unroll
        for (int ks = 0; ks < 4; ks++) {
            uint32_t afr[2][4];
            #pragma unroll
            for (int mt = 0; mt < 2; mt++)
                ldsm4(afr[mt], ab + a_sw[ks] + mt * 2048);
            uint32_t bfr[8][2];
            #pragma unroll
            for (int p = 0; p < 4; p++) {
                uint32_t rr[4];
                ldsm4(rr, bb + b_sw[ks] + p * 2048);
                bfr[2 * p][0]     = rr[0]; bfr[2 * p][1]     = rr[1];
                bfr[2 * p + 1][0] = rr[2]; bfr[2 * p + 1][1] = rr[3];
            }
            #pragma unroll
            for (int mt = 0; mt < 2; mt++)
                #pragma unroll
                for (int ntl = 0; ntl < 8; ntl++)
                    mma_f16(acc[mt][ntl], afr[mt], bfr[ntl]);
        }
    }

    #pragma unroll
    for (int mt = 0; mt < 2; mt++) {
        #pragma unroll
        for (int ntl = 0; ntl < 8; ntl++) {
            int row = m0 + wm * 32 + mt * 16 + g;
            int col = n0 + wn * 64 + ntl * 8 + t * 2;
            float2 bv = *(const float2*)&bias[col];
            #pragma unroll
            for (int half_ = 0; half_ < 2; half_++) {
                int r = row + half_ * 8;
                float v0 = acc[mt][ntl][half_ * 2 + 0] + bv.x;
                float v1 = acc[mt][ntl][half_ * 2 + 1] + bv.y;
                if (ACT == 1) { v0 = gelu_tanh(v0); v1 = gelu_tanh(v1); }
                if (RES) {
                    float2 rr = *(const float2*)&Res[(size_t)r * ldc + col];
                    v0 += rr.x; v1 += rr.y;
                }
                if (OUTH) {
                    __half2* C = (__half2*)((__half*)Cout + (size_t)r * ldc + col);
                    *C = __floats2half2_rn(v0, v1);
                } else {
                    float* C = (float*)Cout + (size_t)r * ldc + col;
                    *(float2*)C = make_float2(v0, v1);
                }
            }
        }
    }
}

// =====================================================================
// Fused flash-attention: P fragments formed directly in registers.
// =====================================================================
#define ATTN_SMEM  ((128*72 + 2*64*72 + 2*64*72) * 2 + 512 * 4)   // 57344

__global__ void __launch_bounds__(256)
attn_kernel(const __half* __restrict__ qkv, const int* __restrict__ seg,
            __half* __restrict__ ctx)
{
    extern __shared__ __half hsm[];
    __half* sP    = hsm;                       // 128*72 (Q staging)
    __half* sK    = sP + 128 * 72;             // 2 * 64*72
    __half* sV    = sK + 2 * 64 * 72;          // 2 * 64*72
    float*  smask = (float*)(sV + 2 * 64 * 72);

    const int bh = blockIdx.y;
    const int b = bh / NH_, h = bh - b * NH_;
    const int q0 = blockIdx.x * 128;

    const __half* qp = qkv + (size_t)b * S_ * QKVN + h * DH_;
    const __half* kp = qp + H_;
    __half* cp = ctx + ((size_t)b * S_ + q0) * H_ + h * DH_;

    const int tid = threadIdx.x, lane = tid & 31, wid = tid >> 5;
    const int g = lane >> 2, t = lane & 3;
    const uint32_t sPb = smem_u32(sP);
    const uint32_t sKb0 = smem_u32(sK);
    const uint32_t sVb0 = smem_u32(sV);

    for (int i = tid; i < S_; i += 256)
        smask[i] = (seg[b * S_ + i] > 0) ? 0.f : -1e9f;

    #pragma unroll
    for (int i = 0; i < 4; i++) {
        int c = i * 256 + tid;
        int row = c >> 3, kc = (c & 7) << 3;
        cp16s(sPb + (uint32_t)row * 144 + ((c & 7) << 4),
              qp + (size_t)(q0 + row) * QKVN + kc);
    }
    asm volatile("cp.async.commit_group;" ::: "memory");
    asm volatile("cp.async.wait_group 0;" ::: "memory");
    __syncthreads();

    const uint32_t a_base = (uint32_t)(wid * 16 + (lane & 15)) * 144 + ((lane >> 4) << 4);
    uint32_t qf[4][4];
    #pragma unroll
    for (int s = 0; s < 4; s++)
        ldsm4(qf[s], sPb + a_base + s * 32);
    __syncthreads();

    auto load_kv = [&](int kt, int buf) {
        int kbase = kt * 64;
        #pragma unroll
        for (int i = 0; i < 2; i++) {
            int c = i * 256 + tid;
            int row = c >> 3, kc = (c & 7) << 3;
            const __half* kg = kp + (size_t)(kbase + row) * QKVN + kc;
            uint32_t d = (uint32_t)row * 144 + ((c & 7) << 4);
            cp16s(sKb0 + buf * 9216 + d, kg);
            cp16s(sVb0 + buf * 9216 + d, kg + H_);
        }
        asm volatile("cp.async.commit_group;" ::: "memory");
    };
    load_kv(0, 0);

    const uint32_t bK_base = (uint32_t)(((lane >> 4) << 3) + (lane & 7)) * 144
                           + (((lane >> 3) & 1) << 4);
    const uint32_t bV_base = (uint32_t)(lane & 15) * 144 + (((lane >> 4) & 1) << 4);

    float m_run[2] = {-1e30f, -1e30f};
    float l_run[2] = {0.f, 0.f};
    float o[8][4];
    #pragma unroll
    for (int ntl = 0; ntl < 8; ntl++)
        #pragma unroll
        for (int r = 0; r < 4; r++) o[ntl][r] = 0.f;

    for (int kt = 0; kt < S_ / 64; kt++) {
        int buf = kt & 1;
        asm volatile("cp.async.wait_group 0;" ::: "memory");
        __syncthreads();
        if (kt + 1 < S_ / 64) load_kv(kt + 1, buf ^ 1);

        uint32_t sKb = sKb0 + buf * 9216;
        uint32_t sVb = sVb0 + buf * 9216;

        // S = Q @ K^T
        float sacc[8][4];
        #pragma unroll
        for (int ntl = 0; ntl < 8; ntl++)
            #pragma unroll
            for (int r = 0; r < 4; r++) sacc[ntl][r] = 0.f;
        #pragma unroll
        for (int s = 0; s < 4; s++) {
            uint32_t bfr[8][2];
            #pragma unroll
            for (int p = 0; p < 4; p++) {
                uint32_t rr[4];
                ldsm4(rr, sKb + bK_base + p * (16 * 144) + s * 32);
                bfr[2 * p][0]     = rr[0]; bfr[2 * p][1]     = rr[1];
                bfr[2 * p + 1][0] = rr[2]; bfr[2 * p + 1][1] = rr[3];
            }
            #pragma unroll
            for (int ntl = 0; ntl < 8; ntl++)
                mma_f16(sacc[ntl], qf[s], bfr[ntl]);
        }

        // scale + mask + online softmax
        float tmax0 = -1e30f, tmax1 = -1e30f;
        #pragma unroll
        for (int ntl = 0; ntl < 8; ntl++) {
            int col = kt * 64 + ntl * 8 + t * 2;
            float mb0 = smask[col], mb1 = smask[col + 1];
            sacc[ntl][0] = fmaf(sacc[ntl][0], 0.125f, mb0);
            sacc[ntl][1] = fmaf(sacc[ntl][1], 0.125f, mb1);
            sacc[ntl][2] = fmaf(sacc[ntl][2], 0.125f, mb0);
            sacc[ntl][3] = fmaf(sacc[ntl][3], 0.125f, mb1);
            tmax0 = fmaxf(tmax0, fmaxf(sacc[ntl][0], sacc[ntl][1]));
            tmax1 = fmaxf(tmax1, fmaxf(sacc[ntl][2], sacc[ntl][3]));
        }
        tmax0 = fmaxf(tmax0, __shfl_xor_sync(0xffffffffu, tmax0, 1));
        tmax0 = fmaxf(tmax0, __shfl_xor_sync(0xffffffffu, tmax0, 2));
        tmax1 = fmaxf(tmax1, __shfl_xor_sync(0xffffffffu, tmax1, 1));
        tmax1 = fmaxf(tmax1, __shfl_xor_sync(0xffffffffu, tmax1, 2));
        float mnew0 = fmaxf(m_run[0], tmax0);
        float mnew1 = fmaxf(m_run[1], tmax1);
        float al0 = __expf(m_run[0] - mnew0);
        float al1 = __expf(m_run[1] - mnew1);
        float ts0 = 0.f, ts1 = 0.f;
        #pragma unroll
        for (int ntl = 0; ntl < 8; ntl++) {
            sacc[ntl][0] = __expf(sacc[ntl][0] - mnew0);
            sacc[ntl][1] = __expf(sacc[ntl][1] - mnew0);
            sacc[ntl][2] = __expf(sacc[ntl][2] - mnew1);
            sacc[ntl][3] = __expf(sacc[ntl][3] - mnew1);
            ts0 += sacc[ntl][0] + sacc[ntl][1];
            ts1 += sacc[ntl][2] + sacc[ntl][3];
        }
        ts0 += __shfl_xor_sync(0xffffffffu, ts0, 1);
        ts0 += __shfl_xor_sync(0xffffffffu, ts0, 2);
        ts1 += __shfl_xor_sync(0xffffffffu, ts1, 1);
        ts1 += __shfl_xor_sync(0xffffffffu, ts1, 2);
        l_run[0] = l_run[0] * al0 + ts0;
        l_run[1] = l_run[1] * al1 + ts1;
        m_run[0] = mnew0; m_run[1] = mnew1;
        #pragma unroll
        for (int ntl = 0; ntl < 8; ntl++) {
            o[ntl][0] *= al0; o[ntl][1] *= al0;
            o[ntl][2] *= al1; o[ntl][3] *= al1;
        }

        // P @ V : P fragments built directly from sacc registers.
        #pragma unroll
        for (int s = 0; s < 4; s++) {
            uint32_t pf[4];
            pf[0] = pack2(sacc[2*s][0],   sacc[2*s][1]);
            pf[1] = pack2(sacc[2*s][2],   sacc[2*s][3]);
            pf[2] = pack2(sacc[2*s+1][0], sacc[2*s+1][1]);
            pf[3] = pack2(sacc[2*s+1][2], sacc[2*s+1][3]);
            uint32_t bfr[8][2];
            #pragma unroll
            for (int p = 0; p < 4; p++) {
                uint32_t rr[4];
                ldsm4t(rr, sVb + bV_base + s * (16 * 144) + p * 32);
                bfr[2 * p][0]     = rr[0]; bfr[2 * p][1]     = rr[1];
                bfr[2 * p + 1][0] = rr[2]; bfr[2 * p + 1][1] = rr[3];
            }
            #pragma unroll
            for (int ntl = 0; ntl < 8; ntl++)
                mma_f16(o[ntl], pf, bfr[ntl]);
        }
    }

    float rl0 = 1.f / l_run[0], rl1 = 1.f / l_run[1];
    int r0 = wid * 16 + g;
    #pragma unroll
    for (int ntl = 0; ntl < 8; ntl++) {
        int col = ntl * 8 + t * 2;
        *(__half2*)&cp[(size_t)r0 * H_ + col] =
            __floats2half2_rn(o[ntl][0] * rl0, o[ntl][1] * rl0);
        *(__half2*)&cp[(size_t)(r0 + 8) * H_ + col] =
            __floats2half2_rn(o[ntl][2] * rl1, o[ntl][3] * rl1);
    }
}

// ---------------- small SIMT GEMM (pooler + classifier only) ----------------
template<int ACT> // 0 none, 2 tanh
__global__ void gemm_kernel(const float* __restrict__ A, const float* __restrict__ Bm,
                            const float* __restrict__ bias, float* __restrict__ C,
                            int M, int N, int K, int lda, int ldb, int ldc)
{
    __shared__ float As[16][65];
    __shared__ float Bs[16][65];

    int m0 = blockIdx.y * 64;
    int n0 = blockIdx.x * 64;
    int tid = threadIdx.x;
    int tx = tid & 15, ty = tid >> 4;

    float acc[4][4] = {};

    for (int k0 = 0; k0 < K; k0 += 16) {
        #pragma unroll
        for (int i = tid; i < 64 * 16; i += 256) {
            int m = i >> 4, k = i & 15;
            int gm = m0 + m, gk = k0 + k;
            As[k][m] = (gm < M && gk < K) ? A[(long)gm * lda + gk] : 0.f;
        }
        #pragma unroll
        for (int i = tid; i < 16 * 64; i += 256) {
            int k = i >> 6, n = i & 63;
            int gk = k0 + k, gn = n0 + n;
            Bs[k][n] = (gk < K && gn < N) ? Bm[(long)gk * ldb + gn] : 0.f;
        }
        __syncthreads();
        #pragma unroll
        for (int k = 0; k < 16; k++) {
            float a[4], bb[4];
            #pragma unroll
            for (int i = 0; i < 4; i++) a[i] = As[k][ty * 4 + i];
            #pragma unroll
            for (int j = 0; j < 4; j++) bb[j] = Bs[k][tx * 4 + j];
            #pragma unroll
            for (int i = 0; i < 4; i++)
                #pragma unroll
                for (int j = 0; j < 4; j++)
                    acc[i][j] = fmaf(a[i], bb[j], acc[i][j]);
        }
        __syncthreads();
    }

    #pragma unroll
    for (int i = 0; i < 4; i++) {
        int gm = m0 + ty * 4 + i;
        if (gm >= M) continue;
        #pragma unroll
        for (int j = 0; j < 4; j++) {
            int gn = n0 + tx * 4 + j;
            if (gn >= N) continue;
            float v = acc[i][j];
            if (bias) v += bias[gn];
            if (ACT == 2) v = tanhf(v);
            C[(long)gm * ldc + gn] = v;
        }
    }
}

// ---------------- log-softmax + NLL loss + output write ----------------
__global__ void loss_kernel(const float* __restrict__ logits, const int* __restrict__ tgt,
                            float* __restrict__ out, int out_size)
{
    int lane = threadIdx.x;
    float lp = 0.f;
    if (lane < B_) {
        const float* row = logits + lane * LAB_;
        float mx = row[0];
        #pragma unroll
        for (int j = 1; j < LAB_; j++) mx = fmaxf(mx, row[j]);
        float s = 0.f;
        #pragma unroll
        for (int j = 0; j < LAB_; j++) s += expf(row[j] - mx);
        lp = row[tgt[lane]] - mx - logf(s);
    }
    #pragma unroll
    for (int o = 16; o; o >>= 1) lp += __shfl_down_sync(0xffffffffu, lp, o);
    int ofs = (out_size > B_ * LAB_) ? 1 : 0;
    if (lane == 0 && ofs) out[0] = -lp / (float)B_;
    for (int i = lane; i < B_ * LAB_; i += 32) out[ofs + i] = logits[i];
}

// ---------------- host launch ----------------
extern "C" void kernel_launch(void* const* d_in, const int* in_sizes, int n_in,
                              void* d_out, int out_size)
{
    const int*   src  = (const int*)d_in[0];
    const int*   seg  = (const int*)d_in[1];
    const int*   tgt  = (const int*)d_in[2];
    const int*   tib  = (const int*)d_in[3];
    const float* we   = (const float*)d_in[4];
    const float* pe   = (const float*)d_in[5];
    const float* se   = (const float*)d_in[6];
    const float* elng = (const float*)d_in[7];
    const float* elnb = (const float*)d_in[8];
    const float* Wq   = (const float*)d_in[9];
    const float* bq   = (const float*)d_in[10];
    const float* Wk   = (const float*)d_in[11];
    const float* bk   = (const float*)d_in[12];
    const float* Wv   = (const float*)d_in[13];
    const float* bv   = (const float*)d_in[14];
    const float* Wo   = (const float*)d_in[15];
    const float* bo   = (const float*)d_in[16];
    const float* ln1g = (const float*)d_in[17];
    const float* ln1b = (const float*)d_in[18];
    const float* Wf1  = (const float*)d_in[19];
    const float* bf1  = (const float*)d_in[20];
    const float* Wf2  = (const float*)d_in[21];
    const float* bf2  = (const float*)d_in[22];
    const float* ln2g = (const float*)d_in[23];
    const float* ln2b = (const float*)d_in[24];
    const float* Wp1  = (const float*)d_in[25];
    const float* bp1  = (const float*)d_in[26];
    const float* Wp2  = (const float*)d_in[27];
    const float* bp2  = (const float*)d_in[28];
    const float* sel  = (const float*)d_in[29];
    (void)in_sizes; (void)n_in;

    float *x, *tmp, *hidden, *logits, *bqkv;
    __half *xh, *qkv, *ctxh, *ffh, *wqkvT, *woT, *wf1T, *wf2T;
    cudaGetSymbolAddress((void**)&x,     g_x);
    cudaGetSymbolAddress((void**)&xh,    g_xh);
    cudaGetSymbolAddress((void**)&qkv,   g_qkv);
    cudaGetSymbolAddress((void**)&ctxh,  g_ctxh);
    cudaGetSymbolAddress((void**)&tmp,   g_tmp);
    cudaGetSymbolAddress((void**)&ffh,   g_ffh);
    cudaGetSymbolAddress((void**)&hidden,g_hidden);
    cudaGetSymbolAddress((void**)&logits,g_logits);
    cudaGetSymbolAddress((void**)&wqkvT, g_wqkvT);
    cudaGetSymbolAddress((void**)&woT,   g_woT);
    cudaGetSymbolAddress((void**)&wf1T,  g_wf1T);
    cudaGetSymbolAddress((void**)&wf2T,  g_wf2T);
    cudaGetSymbolAddress((void**)&bqkv,  g_bqkv);

    cudaFuncSetAttribute((const void*)hgemm<0,1,0>, cudaFuncAttributeMaxDynamicSharedMemorySize, HG_SMEM);
    cudaFuncSetAttribute((const void*)hgemm<0,0,1>, cudaFuncAttributeMaxDynamicSharedMemorySize, HG_SMEM);
    cudaFuncSetAttribute((const void*)hgemm<1,1,0>, cudaFuncAttributeMaxDynamicSharedMemorySize, HG_SMEM);
    cudaFuncSetAttribute((const void*)attn_kernel,  cudaFuncAttributeMaxDynamicSharedMemorySize, ATTN_SMEM);

    const int Mtok = B_ * S_;                    // 8192

    // weight prep
    {
        dim3 tb(32, 8);
        dim3 gHH(H_ / 32, H_ / 32, L_);
        transpose_cvt<<<gHH, tb>>>(Wq, wqkvT,                   H_, H_, (long)QKVN * H_);
        transpose_cvt<<<gHH, tb>>>(Wk, wqkvT + (size_t)H_*H_,   H_, H_, (long)QKVN * H_);
        transpose_cvt<<<gHH, tb>>>(Wv, wqkvT + (size_t)2*H_*H_, H_, H_, (long)QKVN * H_);
        transpose_cvt<<<gHH, tb>>>(Wo, woT, H_, H_, (long)H_ * H_);
        dim3 gF1(FF_ / 32, H_ / 32, L_);
        transpose_cvt<<<gF1, tb>>>(Wf1, wf1T, H_, FF_, (long)FF_ * H_);
        dim3 gF2(H_ / 32, FF_ / 32, L_);
        transpose_cvt<<<gF2, tb>>>(Wf2, wf2T, FF_, H_, (long)H_ * FF_);
        concat_bias<<<(L_ * QKVN + 255) / 256, 256>>>(bq, bk, bv, bqkv);
    }

    embed_kernel<<<Mtok / 8, 256>>>(src, seg, tib, we, pe, se, elng, elnb, sel, x, xh);

    dim3 gQKV(QKVN / 128, Mtok / 128);   // (18, 64)
    dim3 gH  (H_   / 128, Mtok / 128);   // (6, 64)
    dim3 gFF (FF_  / 128, Mtok / 128);   // (24, 64)
    dim3 gAtt(S_ / 128, B_ * NH_);       // (4, 192)

    for (int l = 0; l < L_; l++) {
        const __half* wqkv = wqkvT + (size_t)l * QKVN * H_;
        const __half* wo   = woT   + (size_t)l * H_ * H_;
        const __half* wf1  = wf1T  + (size_t)l * H_ * FF_;
        const __half* wf2  = wf2T  + (size_t)l * FF_ * H_;

        hgemm<0,1,0><<<gQKV, 256, HG_SMEM>>>(xh, wqkv, bqkv + l * QKVN, qkv, nullptr,
                                             H_, H_, H_, QKVN);
        attn_kernel<<<gAtt, 256, ATTN_SMEM>>>(qkv, seg, ctxh);
        // tmp = ctx @ Wo + bo + x  (residual fused)
        hgemm<0,0,1><<<gH, 256, HG_SMEM>>>(ctxh, wo, bo + l * H_, tmp, x,
                                           H_, H_, H_, H_);
        ln_kernel<<<Mtok / 8, 256>>>(tmp, ln1g + l * H_, ln1b + l * H_, x, xh);

        hgemm<1,1,0><<<gFF, 256, HG_SMEM>>>(xh, wf1, bf1 + l * FF_, ffh, nullptr,
                                            H_, H_, H_, FF_);
        // tmp = gelu_ff @ Wf2 + bf2 + x  (residual fused)
        hgemm<0,0,1><<<gH, 256, HG_SMEM>>>(ffh, wf2, bf2 + l * H_, tmp, x,
                                           FF_, FF_, FF_, H_);
        ln_kernel<<<Mtok / 8, 256>>>(tmp, ln2g + l * H_, ln2b + l * H_, x, xh);
    }

    dim3 gPool((H_ + 63) / 64, 1);
    gemm_kernel<2><<<gPool, 256>>>(x, Wp1, bp1, hidden, B_, H_, H_,
                                   S_ * H_, H_, H_);
    dim3 gCls(1, 1);
    gemm_kernel<0><<<gCls, 256>>>(hidden, Wp2, bp2, logits, B_, LAB_, H_,
                                  H_, LAB_, LAB_);

    loss_kernel<<<1, 32>>>(logits, tgt, (float*)d_out, out_size);
}